// round 12
// baseline (speedup 1.0000x reference)
#include <cuda_runtime.h>
#include <cuda_pipeline.h>
#include <math.h>
#include <stdint.h>

#define BATCH  16
#define CH     256
#define NSP    1024      // H*W
#define NHEADS 4
#define HD     64
#define NGRP   32
#define CPG    8

// Scratch (allocation-free: __device__ globals)
__device__ float g_qkv [BATCH * 3 * CH * NSP];   // qkv projections
__device__ float g_att [BATCH * CH * NSP];       // attention output
__device__ float g_s   [BATCH * CH];             // GN scale  (gamma*rstd)
__device__ float g_t   [BATCH * CH];             // GN shift  (beta - mu*scale)
__device__ float g_qb  [BATCH * 3 * CH];         // fused qkv bias: qkv_b + W*t

// ---------------------------------------------------------------------------
// m16n8k8 tf32 mma (raw fp32 bits in, fp32 accum)
// ---------------------------------------------------------------------------
__device__ __forceinline__ void mma8(float d[4],
    uint32_t a0, uint32_t a1, uint32_t a2, uint32_t a3,
    uint32_t b0, uint32_t b1) {
    asm volatile(
        "mma.sync.aligned.m16n8k8.row.col.f32.tf32.tf32.f32 "
        "{%0,%1,%2,%3}, {%4,%5,%6,%7}, {%8,%9}, {%0,%1,%2,%3};\n"
        : "+f"(d[0]), "+f"(d[1]), "+f"(d[2]), "+f"(d[3])
        : "r"(a0), "r"(a1), "r"(a2), "r"(a3), "r"(b0), "r"(b1));
}

// ---------------------------------------------------------------------------
// GN statistics only: per (b,group) mean/rstd -> per-channel scale/shift.
// The normalize pass is folded into the QKV GEMM.
// ---------------------------------------------------------------------------
__global__ void __launch_bounds__(256)
gn_stats(const float* __restrict__ x,
         const float* __restrict__ gamma,
         const float* __restrict__ beta) {
    int b = blockIdx.x >> 5;
    int g = blockIdx.x & 31;
    const float4* xb = (const float4*)(x + ((size_t)b * CH + g * CPG) * NSP);

    float s = 0.f, s2 = 0.f;
    for (int i = threadIdx.x; i < 2048; i += 256) {
        float4 v = xb[i];
        s  += v.x + v.y + v.z + v.w;
        s2 += v.x * v.x + v.y * v.y + v.z * v.z + v.w * v.w;
    }
    __shared__ float rs[256], rq[256];
    rs[threadIdx.x] = s; rq[threadIdx.x] = s2;
    __syncthreads();
    for (int o = 128; o > 0; o >>= 1) {
        if (threadIdx.x < o) {
            rs[threadIdx.x] += rs[threadIdx.x + o];
            rq[threadIdx.x] += rq[threadIdx.x + o];
        }
        __syncthreads();
    }
    if (threadIdx.x < CPG) {
        float mu   = rs[0] * (1.f / 8192.f);
        float var  = rq[0] * (1.f / 8192.f) - mu * mu;
        float rstd = rsqrtf(var + 1e-5f);
        int c = g * CPG + threadIdx.x;
        float sv = gamma[c] * rstd;
        g_s[b * CH + c] = sv;
        g_t[b * CH + c] = beta[c] - mu * sv;
    }
}

// ---------------------------------------------------------------------------
// Fused qkv bias: g_qb[b][m] = qkv_b[m] + sum_k W[m,k]*g_t[b,k]  (exact fp32)
// ---------------------------------------------------------------------------
__global__ void __launch_bounds__(128)
qkv_bias_kernel(const float* __restrict__ W, const float* __restrict__ qkv_b) {
    int b = blockIdx.y;
    int m = blockIdx.x * 128 + threadIdx.x;
    __shared__ float ts[CH];
    if (threadIdx.x < 64)
        *(float4*)&ts[threadIdx.x * 4] = *(const float4*)&g_t[b * CH + threadIdx.x * 4];
    __syncthreads();
    float acc = qkv_b[m];
    const float4* wr = (const float4*)(W + (size_t)m * CH);
    #pragma unroll 8
    for (int k = 0; k < 64; k++) {
        float4 w = wr[k];
        acc += w.x * ts[4 * k] + w.y * ts[4 * k + 1]
             + w.z * ts[4 * k + 2] + w.w * ts[4 * k + 3];
    }
    g_qb[b * 3 * CH + m] = acc;
}

// ---------------------------------------------------------------------------
// Raw-PTX tf32 channel GEMM. QKV mode: reads x (param), writes g_qkv
// (IN-KERNEL — host can't name device globals), A-frags scaled by g_s[b,k],
// bias from g_qb. Proj mode: reads g_att (in-kernel), writes out param,
// bias + residual.
// ---------------------------------------------------------------------------
#define G2_LDW 36
#define G2_LDB 136
#define G2_LDE 132
#define G2_WS  (128 * G2_LDW)    // 4608
#define G2_BS  (32 * G2_LDB)     // 4352
#define G2_FLOATS (2 * G2_WS + 2 * G2_BS + CH)   // +256 for s-vector

template<int MOUT, bool QKV_MODE>
__global__ void __launch_bounds__(256, 2)
gemm_ptx(const float* __restrict__ W, const float* __restrict__ bias,
         const float* __restrict__ inp, const float* __restrict__ resid,
         float* __restrict__ out) {
    extern __shared__ float sm[];
    float* Wbuf = sm;
    float* Bbuf = sm + 2 * G2_WS;
    float* sS   = sm + 2 * G2_WS + 2 * G2_BS;

    int n0 = blockIdx.x * 128;
    int m0 = blockIdx.y * 128;
    int b  = blockIdx.z;
    const float* src = QKV_MODE ? inp : g_att;   // in-kernel scratch binding
    float*       dst = QKV_MODE ? g_qkv : out;   // FIX: output side too
    const float* ib  = src + (size_t)b * CH * NSP;

    int lane = threadIdx.x & 31, warp = threadIdx.x >> 5;
    int g = lane >> 2, t = lane & 3;
    int wm = (warp & 1) * 64;
    int wn = (warp >> 1) * 32;

    if (QKV_MODE && threadIdx.x < 64)
        *(float4*)&sS[threadIdx.x * 4] = *(const float4*)&g_s[b * CH + threadIdx.x * 4];

    float acc[4][4][4];
    #pragma unroll
    for (int mt = 0; mt < 4; mt++)
        #pragma unroll
        for (int nt = 0; nt < 4; nt++)
            #pragma unroll
            for (int c = 0; c < 4; c++) acc[mt][nt][c] = 0.f;

    auto issue = [&](int ch) {
        float* ws = Wbuf + (ch & 1) * G2_WS;
        float* bs = Bbuf + (ch & 1) * G2_BS;
        int k0 = ch * 32;
        #pragma unroll
        for (int idx = threadIdx.x; idx < 1024; idx += 256) {
            int row = idx >> 3, k4 = (idx & 7) * 4;
            __pipeline_memcpy_async(ws + row * G2_LDW + k4,
                W + (size_t)(m0 + row) * CH + k0 + k4, 16);
        }
        #pragma unroll
        for (int idx = threadIdx.x; idx < 1024; idx += 256) {
            int row = idx >> 5, n4 = (idx & 31) * 4;
            __pipeline_memcpy_async(bs + row * G2_LDB + n4,
                ib + (size_t)(k0 + row) * NSP + n0 + n4, 16);
        }
        __pipeline_commit();
    };

    issue(0);
    for (int ch = 0; ch < 8; ch++) {
        float* ws = Wbuf + (ch & 1) * G2_WS;
        float* bs = Bbuf + (ch & 1) * G2_BS;
        __pipeline_wait_prior(0);
        __syncthreads();
        if (ch < 7) issue(ch + 1);
        int k0 = ch * 32;
        #pragma unroll
        for (int k8 = 0; k8 < 4; k8++) {
            int kk = k8 * 8;
            float sv0 = 1.f, sv1 = 1.f;
            if (QKV_MODE) {
                sv0 = sS[k0 + kk + t];
                sv1 = sS[k0 + kk + t + 4];
            }
            uint32_t a[4][4];
            #pragma unroll
            for (int mt = 0; mt < 4; mt++) {
                const float* wr = ws + (wm + mt * 16) * G2_LDW + kk;
                float f0 = wr[g * G2_LDW + t];
                float f1 = wr[(g + 8) * G2_LDW + t];
                float f2 = wr[g * G2_LDW + t + 4];
                float f3 = wr[(g + 8) * G2_LDW + t + 4];
                if (QKV_MODE) { f0 *= sv0; f1 *= sv0; f2 *= sv1; f3 *= sv1; }
                a[mt][0] = __float_as_uint(f0);
                a[mt][1] = __float_as_uint(f1);
                a[mt][2] = __float_as_uint(f2);
                a[mt][3] = __float_as_uint(f3);
            }
            uint32_t bb[4][2];
            #pragma unroll
            for (int nt = 0; nt < 4; nt++) {
                const float* br = bs + kk * G2_LDB + wn + nt * 8 + g;
                bb[nt][0] = __float_as_uint(br[t * G2_LDB]);
                bb[nt][1] = __float_as_uint(br[(t + 4) * G2_LDB]);
            }
            #pragma unroll
            for (int mt = 0; mt < 4; mt++)
                #pragma unroll
                for (int nt = 0; nt < 4; nt++)
                    mma8(acc[mt][nt], a[mt][0], a[mt][1], a[mt][2], a[mt][3],
                         bb[nt][0], bb[nt][1]);
        }
        __syncthreads();
    }

    // Epilogue
    float* Ss = sm;
    #pragma unroll
    for (int mt = 0; mt < 4; mt++) {
        int r0 = wm + mt * 16 + g;
        #pragma unroll
        for (int nt = 0; nt < 4; nt++) {
            int cc = wn + nt * 8 + 2 * t;
            *(float2*)(Ss + r0 * G2_LDE + cc)       = make_float2(acc[mt][nt][0], acc[mt][nt][1]);
            *(float2*)(Ss + (r0 + 8) * G2_LDE + cc) = make_float2(acc[mt][nt][2], acc[mt][nt][3]);
        }
    }
    __syncthreads();
    for (int idx = threadIdx.x; idx < 4096; idx += 256) {
        int row = idx >> 5, n4 = (idx & 31) * 4;
        int m = m0 + row;
        float4 v = *(float4*)(Ss + row * G2_LDE + n4);
        float bv = QKV_MODE ? g_qb[b * MOUT + m] : bias[m];
        v.x += bv; v.y += bv; v.z += bv; v.w += bv;
        if (!QKV_MODE) {
            float4 rr = *(const float4*)(resid + ((size_t)b * MOUT + m) * NSP + n0 + n4);
            v.x += rr.x; v.y += rr.y; v.z += rr.z; v.w += rr.w;
        }
        *(float4*)(dst + ((size_t)b * MOUT + m) * NSP + n0 + n4) = v;
    }
}

// ---------------------------------------------------------------------------
// Flash attention: P kept in registers (C->A fragment layout via shfl);
// K/V double-buffered via cp.async; 2 barriers per tile.
// ---------------------------------------------------------------------------
#define LDQ 136
#define LDP 72
#define LDV 68
#define AQ_OFF 0
#define AK_OFF (64 * LDQ)                 // 8704: two K bufs of 64*72
#define AV_OFF (AK_OFF + 2 * 64 * LDP)    // 17920: two V bufs of 64*68
#define AT2_FLOATS (AV_OFF + 2 * 64 * LDV)  // 26624 floats -> 106496 B

__global__ void __launch_bounds__(256, 2)
attn_reg() {
    extern __shared__ float sm[];
    float* Qs = sm + AQ_OFF;

    int qt = blockIdx.x, hh = blockIdx.y, b = blockIdx.z;
    const float* qb = g_qkv + ((size_t)b * 3 * CH + hh * 3 * HD) * NSP;
    const float* kb = qb + (size_t)HD * NSP;
    const float* vb = qb + (size_t)2 * HD * NSP;
    int n0 = qt * 128;

    int lane = threadIdx.x & 31, warp = threadIdx.x >> 5;
    int g = lane >> 2, t = lane & 3;
    int iw = warp * 16;
    int srcA = (lane & ~3) | (t >> 1);        // shfl src for P cols t
    int srcB = srcA + 2;                      // shfl src for P cols t+4
    bool odd = (t & 1);

    auto issue = [&](int tile) {
        float* kd = sm + AK_OFF + (tile & 1) * (64 * LDP);
        float* vd = sm + AV_OFF + (tile & 1) * (64 * LDV);
        int j0 = tile * 64;
        #pragma unroll
        for (int idx = threadIdx.x; idx < 1024; idx += 256) {
            int dd = idx >> 4, j4 = (idx & 15) * 4;
            __pipeline_memcpy_async(kd + dd * LDP + j4, kb + (size_t)dd * NSP + j0 + j4, 16);
            __pipeline_memcpy_async(vd + dd * LDV + j4, vb + (size_t)dd * NSP + j0 + j4, 16);
        }
        __pipeline_commit();
    };

    issue(0);
    issue(1);

    // Q tile [64 d][128 i], scale 1/sqrt(d)=0.125 folded in
    for (int idx = threadIdx.x; idx < 2048; idx += 256) {
        int dd = idx >> 5, i4 = (idx & 31) * 4;
        float4 v = *(const float4*)(qb + (size_t)dd * NSP + n0 + i4);
        v.x *= 0.125f; v.y *= 0.125f; v.z *= 0.125f; v.w *= 0.125f;
        *(float4*)(Qs + dd * LDQ + i4) = v;
    }

    float o[8][4];
    #pragma unroll
    for (int n = 0; n < 8; n++)
        #pragma unroll
        for (int c = 0; c < 4; c++) o[n][c] = 0.f;
    float m0 = -INFINITY, m1 = -INFINITY, l0 = 0.f, l1 = 0.f;

    for (int tile = 0; tile < 16; tile++) {
        __pipeline_wait_prior(tile < 15 ? 1 : 0);
        __syncthreads();   // tile's K/V visible; Q visible on first pass
        float* Ks = sm + AK_OFF + (tile & 1) * (64 * LDP);
        float* Vs = sm + AV_OFF + (tile & 1) * (64 * LDV);

        // S = (Q*scale)^T K
        float s[8][4];
        #pragma unroll
        for (int n = 0; n < 8; n++)
            #pragma unroll
            for (int c = 0; c < 4; c++) s[n][c] = 0.f;
        #pragma unroll
        for (int k = 0; k < 8; k++) {
            int d0 = k * 8;
            uint32_t a0 = __float_as_uint(Qs[(d0 + t)     * LDQ + iw + g]);
            uint32_t a1 = __float_as_uint(Qs[(d0 + t)     * LDQ + iw + g + 8]);
            uint32_t a2 = __float_as_uint(Qs[(d0 + t + 4) * LDQ + iw + g]);
            uint32_t a3 = __float_as_uint(Qs[(d0 + t + 4) * LDQ + iw + g + 8]);
            #pragma unroll
            for (int n = 0; n < 8; n++) {
                uint32_t b0 = __float_as_uint(Ks[(d0 + t)     * LDP + n * 8 + g]);
                uint32_t b1 = __float_as_uint(Ks[(d0 + t + 4) * LDP + n * 8 + g]);
                mma8(s[n], a0, a1, a2, a3, b0, b1);
            }
        }

        // In-register online softmax
        float mx0 = -INFINITY, mx1 = -INFINITY;
        #pragma unroll
        for (int n = 0; n < 8; n++) {
            mx0 = fmaxf(mx0, fmaxf(s[n][0], s[n][1]));
            mx1 = fmaxf(mx1, fmaxf(s[n][2], s[n][3]));
        }
        mx0 = fmaxf(mx0, __shfl_xor_sync(0xffffffffu, mx0, 1));
        mx0 = fmaxf(mx0, __shfl_xor_sync(0xffffffffu, mx0, 2));
        mx1 = fmaxf(mx1, __shfl_xor_sync(0xffffffffu, mx1, 1));
        mx1 = fmaxf(mx1, __shfl_xor_sync(0xffffffffu, mx1, 2));
        float mn0 = fmaxf(m0, mx0), mn1 = fmaxf(m1, mx1);
        float al0 = __expf(m0 - mn0), al1 = __expf(m1 - mn1);
        m0 = mn0; m1 = mn1;
        float r0 = 0.f, r1 = 0.f;
        #pragma unroll
        for (int n = 0; n < 8; n++) {
            s[n][0] = __expf(s[n][0] - mn0);
            s[n][1] = __expf(s[n][1] - mn0);
            s[n][2] = __expf(s[n][2] - mn1);
            s[n][3] = __expf(s[n][3] - mn1);
            r0 += s[n][0] + s[n][1];
            r1 += s[n][2] + s[n][3];
        }
        r0 += __shfl_xor_sync(0xffffffffu, r0, 1);
        r0 += __shfl_xor_sync(0xffffffffu, r0, 2);
        r1 += __shfl_xor_sync(0xffffffffu, r1, 1);
        r1 += __shfl_xor_sync(0xffffffffu, r1, 2);
        l0 = l0 * al0 + r0;
        l1 = l1 * al1 + r1;
        #pragma unroll
        for (int n = 0; n < 8; n++) {
            o[n][0] *= al0; o[n][1] *= al0;
            o[n][2] *= al1; o[n][3] *= al1;
        }

        // O += P V^T. P C-frags -> A-frags via shfl (no smem, no barrier).
        #pragma unroll
        for (int j = 0; j < 8; j++) {
            float v0, v1;
            v0 = __shfl_sync(0xffffffffu, s[j][0], srcA);
            v1 = __shfl_sync(0xffffffffu, s[j][1], srcA);
            uint32_t a0 = __float_as_uint(odd ? v1 : v0);
            v0 = __shfl_sync(0xffffffffu, s[j][2], srcA);
            v1 = __shfl_sync(0xffffffffu, s[j][3], srcA);
            uint32_t a1 = __float_as_uint(odd ? v1 : v0);
            v0 = __shfl_sync(0xffffffffu, s[j][0], srcB);
            v1 = __shfl_sync(0xffffffffu, s[j][1], srcB);
            uint32_t a2 = __float_as_uint(odd ? v1 : v0);
            v0 = __shfl_sync(0xffffffffu, s[j][2], srcB);
            v1 = __shfl_sync(0xffffffffu, s[j][3], srcB);
            uint32_t a3 = __float_as_uint(odd ? v1 : v0);
            int jj = j * 8;
            #pragma unroll
            for (int n = 0; n < 8; n++) {
                uint32_t b0 = __float_as_uint(Vs[(n * 8 + g) * LDV + jj + t]);
                uint32_t b1 = __float_as_uint(Vs[(n * 8 + g) * LDV + jj + t + 4]);
                mma8(o[n], a0, a1, a2, a3, b0, b1);
            }
        }
        __syncthreads();          // all warps done reading buf (tile&1)
        if (tile < 14) issue(tile + 2);
    }

    // Normalize, stage transposed [dc][i] (reuse K region), coalesced store
    float inv0 = 1.f / l0, inv1 = 1.f / l1;
    #pragma unroll
    for (int n = 0; n < 8; n++) {
        o[n][0] *= inv0; o[n][1] *= inv0;
        o[n][2] *= inv1; o[n][3] *= inv1;
    }
    float* Os = sm + AK_OFF;   // 64 x 132 = 8448 <= 9216
    #pragma unroll
    for (int n = 0; n < 8; n++) {
        int dc = n * 8 + 2 * t;
        Os[dc * 132 + iw + g]           = o[n][0];
        Os[(dc + 1) * 132 + iw + g]     = o[n][1];
        Os[dc * 132 + iw + g + 8]       = o[n][2];
        Os[(dc + 1) * 132 + iw + g + 8] = o[n][3];
    }
    __syncthreads();
    float* ob = g_att + ((size_t)b * CH + hh * HD) * NSP + n0;
    for (int idx = threadIdx.x; idx < 2048; idx += 256) {
        int dc = idx >> 5, i4 = (idx & 31) * 4;
        *(float4*)(ob + (size_t)dc * NSP + i4) = *(float4*)(Os + dc * 132 + i4);
    }
}

// ---------------------------------------------------------------------------

extern "C" void kernel_launch(void* const* d_in, const int* in_sizes, int n_in,
                              void* d_out, int out_size) {
    const float* x      = (const float*)d_in[0];
    const float* gamma  = (const float*)d_in[1];
    const float* beta   = (const float*)d_in[2];
    const float* qkv_w  = (const float*)d_in[3];
    const float* qkv_b  = (const float*)d_in[4];
    const float* proj_w = (const float*)d_in[5];
    const float* proj_b = (const float*)d_in[6];
    float* out = (float*)d_out;

    const int gm_smem  = G2_FLOATS * 4;
    const int att_smem = AT2_FLOATS * 4;

    cudaFuncSetAttribute(gemm_ptx<768, true>,
                         cudaFuncAttributeMaxDynamicSharedMemorySize, gm_smem);
    cudaFuncSetAttribute(gemm_ptx<256, false>,
                         cudaFuncAttributeMaxDynamicSharedMemorySize, gm_smem);
    cudaFuncSetAttribute(attn_reg,
                         cudaFuncAttributeMaxDynamicSharedMemorySize, att_smem);

    gn_stats<<<BATCH * NGRP, 256>>>(x, gamma, beta);
    qkv_bias_kernel<<<dim3(6, BATCH), 128>>>(qkv_w, qkv_b);
    gemm_ptx<768, true ><<<dim3(8, 6, BATCH), 256, gm_smem>>>(qkv_w, qkv_b /*unused*/, x, x /*unused*/, out /*unused*/);
    attn_reg<<<dim3(NSP / 128, NHEADS, BATCH), 256, att_smem>>>();
    gemm_ptx<256, false><<<dim3(8, 2, BATCH), 256, gm_smem>>>(proj_w, proj_b, x /*unused*/, x, out);
}

// round 13
// speedup vs baseline: 1.3078x; 1.3078x over previous
#include <cuda_runtime.h>
#include <cuda_pipeline.h>
#include <math.h>
#include <stdint.h>

#define BATCH  16
#define CH     256
#define NSP    1024      // H*W
#define NHEADS 4
#define HD     64
#define NGRP   32
#define CPG    8

// Scratch (allocation-free: __device__ globals)
__device__ float g_qkv [BATCH * 3 * CH * NSP];   // qkv projections
__device__ float g_att [BATCH * CH * NSP];       // attention output
__device__ float g_s   [BATCH * CH];             // GN scale  (gamma*rstd)
__device__ float g_t   [BATCH * CH];             // GN shift  (beta - mu*scale)
__device__ float g_qb  [BATCH * 3 * CH];         // fused qkv bias: qkv_b + W*t

// ---------------------------------------------------------------------------
// m16n8k8 tf32 mma (raw fp32 bits in, fp32 accum)
// ---------------------------------------------------------------------------
__device__ __forceinline__ void mma8(float d[4],
    uint32_t a0, uint32_t a1, uint32_t a2, uint32_t a3,
    uint32_t b0, uint32_t b1) {
    asm volatile(
        "mma.sync.aligned.m16n8k8.row.col.f32.tf32.tf32.f32 "
        "{%0,%1,%2,%3}, {%4,%5,%6,%7}, {%8,%9}, {%0,%1,%2,%3};\n"
        : "+f"(d[0]), "+f"(d[1]), "+f"(d[2]), "+f"(d[3])
        : "r"(a0), "r"(a1), "r"(a2), "r"(a3), "r"(b0), "r"(b1));
}

// ---------------------------------------------------------------------------
// GN statistics only: per (b,group) mean/rstd -> per-channel scale/shift.
// ---------------------------------------------------------------------------
__global__ void __launch_bounds__(256)
gn_stats(const float* __restrict__ x,
         const float* __restrict__ gamma,
         const float* __restrict__ beta) {
    int b = blockIdx.x >> 5;
    int g = blockIdx.x & 31;
    const float4* xb = (const float4*)(x + ((size_t)b * CH + g * CPG) * NSP);

    float s = 0.f, s2 = 0.f;
    for (int i = threadIdx.x; i < 2048; i += 256) {
        float4 v = xb[i];
        s  += v.x + v.y + v.z + v.w;
        s2 += v.x * v.x + v.y * v.y + v.z * v.z + v.w * v.w;
    }
    __shared__ float rs[256], rq[256];
    rs[threadIdx.x] = s; rq[threadIdx.x] = s2;
    __syncthreads();
    for (int o = 128; o > 0; o >>= 1) {
        if (threadIdx.x < o) {
            rs[threadIdx.x] += rs[threadIdx.x + o];
            rq[threadIdx.x] += rq[threadIdx.x + o];
        }
        __syncthreads();
    }
    if (threadIdx.x < CPG) {
        float mu   = rs[0] * (1.f / 8192.f);
        float var  = rq[0] * (1.f / 8192.f) - mu * mu;
        float rstd = rsqrtf(var + 1e-5f);
        int c = g * CPG + threadIdx.x;
        float sv = gamma[c] * rstd;
        g_s[b * CH + c] = sv;
        g_t[b * CH + c] = beta[c] - mu * sv;
    }
}

// ---------------------------------------------------------------------------
// Fused qkv bias: g_qb[b][m] = qkv_b[m] + sum_k W[m,k]*g_t[b,k]  (exact fp32)
// ---------------------------------------------------------------------------
__global__ void __launch_bounds__(128)
qkv_bias_kernel(const float* __restrict__ W, const float* __restrict__ qkv_b) {
    int b = blockIdx.y;
    int m = blockIdx.x * 128 + threadIdx.x;
    __shared__ float ts[CH];
    if (threadIdx.x < 64)
        *(float4*)&ts[threadIdx.x * 4] = *(const float4*)&g_t[b * CH + threadIdx.x * 4];
    __syncthreads();
    float acc = qkv_b[m];
    const float4* wr = (const float4*)(W + (size_t)m * CH);
    #pragma unroll 8
    for (int k = 0; k < 64; k++) {
        float4 w = wr[k];
        acc += w.x * ts[4 * k] + w.y * ts[4 * k + 1]
             + w.z * ts[4 * k + 2] + w.w * ts[4 * k + 3];
    }
    g_qb[b * 3 * CH + m] = acc;
}

// ---------------------------------------------------------------------------
// Raw-PTX tf32 channel GEMM (verbatim from passing R12).
// QKV mode: reads x (param), writes g_qkv (in-kernel binding), A-frags scaled
// by g_s[b,k], bias g_qb. Proj mode: reads g_att (in-kernel), bias+residual.
// ---------------------------------------------------------------------------
#define G2_LDW 36
#define G2_LDB 136
#define G2_LDE 132
#define G2_WS  (128 * G2_LDW)    // 4608
#define G2_BS  (32 * G2_LDB)     // 4352
#define G2_FLOATS (2 * G2_WS + 2 * G2_BS + CH)

template<int MOUT, bool QKV_MODE>
__global__ void __launch_bounds__(256, 2)
gemm_ptx(const float* __restrict__ W, const float* __restrict__ bias,
         const float* __restrict__ inp, const float* __restrict__ resid,
         float* __restrict__ out) {
    extern __shared__ float sm[];
    float* Wbuf = sm;
    float* Bbuf = sm + 2 * G2_WS;
    float* sS   = sm + 2 * G2_WS + 2 * G2_BS;

    int n0 = blockIdx.x * 128;
    int m0 = blockIdx.y * 128;
    int b  = blockIdx.z;
    const float* src = QKV_MODE ? inp : g_att;
    float*       dst = QKV_MODE ? g_qkv : out;
    const float* ib  = src + (size_t)b * CH * NSP;

    int lane = threadIdx.x & 31, warp = threadIdx.x >> 5;
    int g = lane >> 2, t = lane & 3;
    int wm = (warp & 1) * 64;
    int wn = (warp >> 1) * 32;

    if (QKV_MODE && threadIdx.x < 64)
        *(float4*)&sS[threadIdx.x * 4] = *(const float4*)&g_s[b * CH + threadIdx.x * 4];

    float acc[4][4][4];
    #pragma unroll
    for (int mt = 0; mt < 4; mt++)
        #pragma unroll
        for (int nt = 0; nt < 4; nt++)
            #pragma unroll
            for (int c = 0; c < 4; c++) acc[mt][nt][c] = 0.f;

    auto issue = [&](int ch) {
        float* ws = Wbuf + (ch & 1) * G2_WS;
        float* bs = Bbuf + (ch & 1) * G2_BS;
        int k0 = ch * 32;
        #pragma unroll
        for (int idx = threadIdx.x; idx < 1024; idx += 256) {
            int row = idx >> 3, k4 = (idx & 7) * 4;
            __pipeline_memcpy_async(ws + row * G2_LDW + k4,
                W + (size_t)(m0 + row) * CH + k0 + k4, 16);
        }
        #pragma unroll
        for (int idx = threadIdx.x; idx < 1024; idx += 256) {
            int row = idx >> 5, n4 = (idx & 31) * 4;
            __pipeline_memcpy_async(bs + row * G2_LDB + n4,
                ib + (size_t)(k0 + row) * NSP + n0 + n4, 16);
        }
        __pipeline_commit();
    };

    issue(0);
    for (int ch = 0; ch < 8; ch++) {
        float* ws = Wbuf + (ch & 1) * G2_WS;
        float* bs = Bbuf + (ch & 1) * G2_BS;
        __pipeline_wait_prior(0);
        __syncthreads();
        if (ch < 7) issue(ch + 1);
        int k0 = ch * 32;
        #pragma unroll
        for (int k8 = 0; k8 < 4; k8++) {
            int kk = k8 * 8;
            float sv0 = 1.f, sv1 = 1.f;
            if (QKV_MODE) {
                sv0 = sS[k0 + kk + t];
                sv1 = sS[k0 + kk + t + 4];
            }
            uint32_t a[4][4];
            #pragma unroll
            for (int mt = 0; mt < 4; mt++) {
                const float* wr = ws + (wm + mt * 16) * G2_LDW + kk;
                float f0 = wr[g * G2_LDW + t];
                float f1 = wr[(g + 8) * G2_LDW + t];
                float f2 = wr[g * G2_LDW + t + 4];
                float f3 = wr[(g + 8) * G2_LDW + t + 4];
                if (QKV_MODE) { f0 *= sv0; f1 *= sv0; f2 *= sv1; f3 *= sv1; }
                a[mt][0] = __float_as_uint(f0);
                a[mt][1] = __float_as_uint(f1);
                a[mt][2] = __float_as_uint(f2);
                a[mt][3] = __float_as_uint(f3);
            }
            uint32_t bb[4][2];
            #pragma unroll
            for (int nt = 0; nt < 4; nt++) {
                const float* br = bs + kk * G2_LDB + wn + nt * 8 + g;
                bb[nt][0] = __float_as_uint(br[t * G2_LDB]);
                bb[nt][1] = __float_as_uint(br[(t + 4) * G2_LDB]);
            }
            #pragma unroll
            for (int mt = 0; mt < 4; mt++)
                #pragma unroll
                for (int nt = 0; nt < 4; nt++)
                    mma8(acc[mt][nt], a[mt][0], a[mt][1], a[mt][2], a[mt][3],
                         bb[nt][0], bb[nt][1]);
        }
        __syncthreads();
    }

    float* Ss = sm;
    #pragma unroll
    for (int mt = 0; mt < 4; mt++) {
        int r0 = wm + mt * 16 + g;
        #pragma unroll
        for (int nt = 0; nt < 4; nt++) {
            int cc = wn + nt * 8 + 2 * t;
            *(float2*)(Ss + r0 * G2_LDE + cc)       = make_float2(acc[mt][nt][0], acc[mt][nt][1]);
            *(float2*)(Ss + (r0 + 8) * G2_LDE + cc) = make_float2(acc[mt][nt][2], acc[mt][nt][3]);
        }
    }
    __syncthreads();
    for (int idx = threadIdx.x; idx < 4096; idx += 256) {
        int row = idx >> 5, n4 = (idx & 31) * 4;
        int m = m0 + row;
        float4 v = *(float4*)(Ss + row * G2_LDE + n4);
        float bv = QKV_MODE ? g_qb[b * MOUT + m] : bias[m];
        v.x += bv; v.y += bv; v.z += bv; v.w += bv;
        if (!QKV_MODE) {
            float4 rr = *(const float4*)(resid + ((size_t)b * MOUT + m) * NSP + n0 + n4);
            v.x += rr.x; v.y += rr.y; v.z += rr.z; v.w += rr.w;
        }
        *(float4*)(dst + ((size_t)b * MOUT + m) * NSP + n0 + n4) = v;
    }
}

// ---------------------------------------------------------------------------
// Flash attention v3: P through DEDICATED per-warp smem (no aliasing ->
// only __syncwarp between P store/load; 2 block barriers per tile).
// s[] dies at P store -> regs ~100, no spills. 2 CTAs/SM.
// ---------------------------------------------------------------------------
#define LDQ 136
#define LDK 72
#define LDV 68
#define LDP 72
#define AQ_OFF 0
#define AK_OFF (64 * LDQ)                 // 8704
#define AV_OFF (AK_OFF + 64 * LDK)        // 13312
#define AP_OFF (AV_OFF + 64 * LDV)        // 17664
#define AT3_FLOATS (AP_OFF + 128 * LDP)   // 26880 floats -> 107520 B

__global__ void __launch_bounds__(256, 2)
attn_v3() {
    extern __shared__ float sm[];
    float* Qs = sm + AQ_OFF;
    float* Ks = sm + AK_OFF;
    float* Vs = sm + AV_OFF;
    float* Ps = sm + AP_OFF;   // per-warp rows, never cross-warp

    int qt = blockIdx.x, hh = blockIdx.y, b = blockIdx.z;
    const float* qb = g_qkv + ((size_t)b * 3 * CH + hh * 3 * HD) * NSP;
    const float* kb = qb + (size_t)HD * NSP;
    const float* vb = qb + (size_t)2 * HD * NSP;
    int n0 = qt * 128;

    int lane = threadIdx.x & 31, warp = threadIdx.x >> 5;
    int g = lane >> 2, t = lane & 3;
    int iw = warp * 16;

    // Q tile [64 d][128 i], scale 1/sqrt(d)=0.125 folded in
    for (int idx = threadIdx.x; idx < 2048; idx += 256) {
        int dd = idx >> 5, i4 = (idx & 31) * 4;
        float4 v = *(const float4*)(qb + (size_t)dd * NSP + n0 + i4);
        v.x *= 0.125f; v.y *= 0.125f; v.z *= 0.125f; v.w *= 0.125f;
        *(float4*)(Qs + dd * LDQ + i4) = v;
    }

    float o[8][4];
    #pragma unroll
    for (int n = 0; n < 8; n++)
        #pragma unroll
        for (int c = 0; c < 4; c++) o[n][c] = 0.f;
    float m0 = -INFINITY, m1 = -INFINITY, l0 = 0.f, l1 = 0.f;

    for (int tile = 0; tile < 16; tile++) {
        int j0 = tile * 64;
        for (int idx = threadIdx.x; idx < 1024; idx += 256) {
            int dd = idx >> 4, j4 = (idx & 15) * 4;
            *(float4*)(Ks + dd * LDK + j4) = *(const float4*)(kb + (size_t)dd * NSP + j0 + j4);
            *(float4*)(Vs + dd * LDV + j4) = *(const float4*)(vb + (size_t)dd * NSP + j0 + j4);
        }
        __syncthreads();   // K/V ready (and Q on tile 0)

        // S = (Q*scale)^T K
        float s[8][4];
        #pragma unroll
        for (int n = 0; n < 8; n++)
            #pragma unroll
            for (int c = 0; c < 4; c++) s[n][c] = 0.f;
        #pragma unroll
        for (int k = 0; k < 8; k++) {
            int d0 = k * 8;
            uint32_t a0 = __float_as_uint(Qs[(d0 + t)     * LDQ + iw + g]);
            uint32_t a1 = __float_as_uint(Qs[(d0 + t)     * LDQ + iw + g + 8]);
            uint32_t a2 = __float_as_uint(Qs[(d0 + t + 4) * LDQ + iw + g]);
            uint32_t a3 = __float_as_uint(Qs[(d0 + t + 4) * LDQ + iw + g + 8]);
            #pragma unroll
            for (int n = 0; n < 8; n++) {
                uint32_t b0 = __float_as_uint(Ks[(d0 + t)     * LDK + n * 8 + g]);
                uint32_t b1 = __float_as_uint(Ks[(d0 + t + 4) * LDK + n * 8 + g]);
                mma8(s[n], a0, a1, a2, a3, b0, b1);
            }
        }

        // In-register online softmax (row reduce over 4-lane groups)
        float mx0 = -INFINITY, mx1 = -INFINITY;
        #pragma unroll
        for (int n = 0; n < 8; n++) {
            mx0 = fmaxf(mx0, fmaxf(s[n][0], s[n][1]));
            mx1 = fmaxf(mx1, fmaxf(s[n][2], s[n][3]));
        }
        mx0 = fmaxf(mx0, __shfl_xor_sync(0xffffffffu, mx0, 1));
        mx0 = fmaxf(mx0, __shfl_xor_sync(0xffffffffu, mx0, 2));
        mx1 = fmaxf(mx1, __shfl_xor_sync(0xffffffffu, mx1, 1));
        mx1 = fmaxf(mx1, __shfl_xor_sync(0xffffffffu, mx1, 2));
        float mn0 = fmaxf(m0, mx0), mn1 = fmaxf(m1, mx1);
        float al0 = __expf(m0 - mn0), al1 = __expf(m1 - mn1);
        m0 = mn0; m1 = mn1;
        float r0 = 0.f, r1 = 0.f;
        #pragma unroll
        for (int n = 0; n < 8; n++) {
            s[n][0] = __expf(s[n][0] - mn0);
            s[n][1] = __expf(s[n][1] - mn0);
            s[n][2] = __expf(s[n][2] - mn1);
            s[n][3] = __expf(s[n][3] - mn1);
            r0 += s[n][0] + s[n][1];
            r1 += s[n][2] + s[n][3];
        }
        r0 += __shfl_xor_sync(0xffffffffu, r0, 1);
        r0 += __shfl_xor_sync(0xffffffffu, r0, 2);
        r1 += __shfl_xor_sync(0xffffffffu, r1, 1);
        r1 += __shfl_xor_sync(0xffffffffu, r1, 2);
        l0 = l0 * al0 + r0;
        l1 = l1 * al1 + r1;

        // Store P into this warp's own rows (C frag cols 2t,2t+1)
        #pragma unroll
        for (int n = 0; n < 8; n++) {
            *(float2*)(Ps + (iw + g)     * LDP + n * 8 + 2 * t) = make_float2(s[n][0], s[n][1]);
            *(float2*)(Ps + (iw + g + 8) * LDP + n * 8 + 2 * t) = make_float2(s[n][2], s[n][3]);
        }
        __syncwarp();   // warp-private region: warp-level ordering suffices

        // Rescale O
        #pragma unroll
        for (int n = 0; n < 8; n++) {
            o[n][0] *= al0; o[n][1] *= al0;
            o[n][2] *= al1; o[n][3] *= al1;
        }

        // O += P V^T : A(i,j)=P[iw+i][jj+j], B(j,dc)=V[n8+dc][jj+j]
        #pragma unroll
        for (int j = 0; j < 8; j++) {
            int jj = j * 8;
            uint32_t a0 = __float_as_uint(Ps[(iw + g)     * LDP + jj + t]);
            uint32_t a1 = __float_as_uint(Ps[(iw + g + 8) * LDP + jj + t]);
            uint32_t a2 = __float_as_uint(Ps[(iw + g)     * LDP + jj + t + 4]);
            uint32_t a3 = __float_as_uint(Ps[(iw + g + 8) * LDP + jj + t + 4]);
            #pragma unroll
            for (int n = 0; n < 8; n++) {
                uint32_t b0 = __float_as_uint(Vs[(n * 8 + g) * LDV + jj + t]);
                uint32_t b1 = __float_as_uint(Vs[(n * 8 + g) * LDV + jj + t + 4]);
                mma8(o[n], a0, a1, a2, a3, b0, b1);
            }
        }
        __syncthreads();   // all warps done with K/V before next tile's load
    }

    // Normalize, stage transposed [dc][i] in P region, coalesced store
    float inv0 = 1.f / l0, inv1 = 1.f / l1;
    #pragma unroll
    for (int n = 0; n < 8; n++) {
        o[n][0] *= inv0; o[n][1] *= inv0;
        o[n][2] *= inv1; o[n][3] *= inv1;
    }
    float* Os = sm + AP_OFF;   // 64 x 132 = 8448 <= 9216
    #pragma unroll
    for (int n = 0; n < 8; n++) {
        int dc = n * 8 + 2 * t;
        Os[dc * 132 + iw + g]           = o[n][0];
        Os[(dc + 1) * 132 + iw + g]     = o[n][1];
        Os[dc * 132 + iw + g + 8]       = o[n][2];
        Os[(dc + 1) * 132 + iw + g + 8] = o[n][3];
    }
    __syncthreads();
    float* ob = g_att + ((size_t)b * CH + hh * HD) * NSP + n0;
    for (int idx = threadIdx.x; idx < 2048; idx += 256) {
        int dc = idx >> 5, i4 = (idx & 31) * 4;
        *(float4*)(ob + (size_t)dc * NSP + i4) = *(float4*)(Os + dc * 132 + i4);
    }
}

// ---------------------------------------------------------------------------

extern "C" void kernel_launch(void* const* d_in, const int* in_sizes, int n_in,
                              void* d_out, int out_size) {
    const float* x      = (const float*)d_in[0];
    const float* gamma  = (const float*)d_in[1];
    const float* beta   = (const float*)d_in[2];
    const float* qkv_w  = (const float*)d_in[3];
    const float* qkv_b  = (const float*)d_in[4];
    const float* proj_w = (const float*)d_in[5];
    const float* proj_b = (const float*)d_in[6];
    float* out = (float*)d_out;

    const int gm_smem  = G2_FLOATS * 4;
    const int att_smem = AT3_FLOATS * 4;

    cudaFuncSetAttribute(gemm_ptx<768, true>,
                         cudaFuncAttributeMaxDynamicSharedMemorySize, gm_smem);
    cudaFuncSetAttribute(gemm_ptx<256, false>,
                         cudaFuncAttributeMaxDynamicSharedMemorySize, gm_smem);
    cudaFuncSetAttribute(attn_v3,
                         cudaFuncAttributeMaxDynamicSharedMemorySize, att_smem);

    gn_stats<<<BATCH * NGRP, 256>>>(x, gamma, beta);
    qkv_bias_kernel<<<dim3(6, BATCH), 128>>>(qkv_w, qkv_b);
    gemm_ptx<768, true ><<<dim3(8, 6, BATCH), 256, gm_smem>>>(qkv_w, qkv_b /*unused*/, x, x /*unused*/, out /*unused*/);
    attn_v3<<<dim3(NSP / 128, NHEADS, BATCH), 256, att_smem>>>();
    gemm_ptx<256, false><<<dim3(8, 2, BATCH), 256, gm_smem>>>(proj_w, proj_b, x /*unused*/, x, out);
}

// round 14
// speedup vs baseline: 1.4145x; 1.0816x over previous
#include <cuda_runtime.h>
#include <cuda_pipeline.h>
#include <math.h>
#include <stdint.h>

#define BATCH  16
#define CH     256
#define NSP    1024      // H*W
#define NHEADS 4
#define HD     64
#define NGRP   32
#define CPG    8

// Scratch (allocation-free: __device__ globals)
__device__ float g_qkv [BATCH * 3 * CH * NSP];   // qkv projections
__device__ float g_att [BATCH * CH * NSP];       // attention output
__device__ float g_s   [BATCH * CH];             // GN scale  (gamma*rstd)
__device__ float g_t   [BATCH * CH];             // GN shift  (beta - mu*scale)
__device__ float g_qb  [BATCH * 3 * CH];         // fused qkv bias: qkv_b + W*t

// ---------------------------------------------------------------------------
// m16n8k8 tf32 mma (raw fp32 bits in, fp32 accum) + ldmatrix x4
// ---------------------------------------------------------------------------
__device__ __forceinline__ void mma8(float d[4],
    uint32_t a0, uint32_t a1, uint32_t a2, uint32_t a3,
    uint32_t b0, uint32_t b1) {
    asm volatile(
        "mma.sync.aligned.m16n8k8.row.col.f32.tf32.tf32.f32 "
        "{%0,%1,%2,%3}, {%4,%5,%6,%7}, {%8,%9}, {%0,%1,%2,%3};\n"
        : "+f"(d[0]), "+f"(d[1]), "+f"(d[2]), "+f"(d[3])
        : "r"(a0), "r"(a1), "r"(a2), "r"(a3), "r"(b0), "r"(b1));
}

__device__ __forceinline__ void ldsm4(uint32_t& r0, uint32_t& r1,
                                      uint32_t& r2, uint32_t& r3, uint32_t a) {
    asm volatile("ldmatrix.sync.aligned.m8n8.x4.shared.b16 {%0,%1,%2,%3}, [%4];"
        : "=r"(r0), "=r"(r1), "=r"(r2), "=r"(r3) : "r"(a));
}

// ---------------------------------------------------------------------------
// GN statistics only: per (b,group) mean/rstd -> per-channel scale/shift.
// ---------------------------------------------------------------------------
__global__ void __launch_bounds__(256)
gn_stats(const float* __restrict__ x,
         const float* __restrict__ gamma,
         const float* __restrict__ beta) {
    int b = blockIdx.x >> 5;
    int g = blockIdx.x & 31;
    const float4* xb = (const float4*)(x + ((size_t)b * CH + g * CPG) * NSP);

    float s = 0.f, s2 = 0.f;
    for (int i = threadIdx.x; i < 2048; i += 256) {
        float4 v = xb[i];
        s  += v.x + v.y + v.z + v.w;
        s2 += v.x * v.x + v.y * v.y + v.z * v.z + v.w * v.w;
    }
    __shared__ float rs[256], rq[256];
    rs[threadIdx.x] = s; rq[threadIdx.x] = s2;
    __syncthreads();
    for (int o = 128; o > 0; o >>= 1) {
        if (threadIdx.x < o) {
            rs[threadIdx.x] += rs[threadIdx.x + o];
            rq[threadIdx.x] += rq[threadIdx.x + o];
        }
        __syncthreads();
    }
    if (threadIdx.x < CPG) {
        float mu   = rs[0] * (1.f / 8192.f);
        float var  = rq[0] * (1.f / 8192.f) - mu * mu;
        float rstd = rsqrtf(var + 1e-5f);
        int c = g * CPG + threadIdx.x;
        float sv = gamma[c] * rstd;
        g_s[b * CH + c] = sv;
        g_t[b * CH + c] = beta[c] - mu * sv;
    }
}

// ---------------------------------------------------------------------------
// Fused qkv bias: g_qb[b][m] = qkv_b[m] + sum_k W[m,k]*g_t[b,k]  (exact fp32)
// ---------------------------------------------------------------------------
__global__ void __launch_bounds__(128)
qkv_bias_kernel(const float* __restrict__ W, const float* __restrict__ qkv_b) {
    int b = blockIdx.y;
    int m = blockIdx.x * 128 + threadIdx.x;
    __shared__ float ts[CH];
    if (threadIdx.x < 64)
        *(float4*)&ts[threadIdx.x * 4] = *(const float4*)&g_t[b * CH + threadIdx.x * 4];
    __syncthreads();
    float acc = qkv_b[m];
    const float4* wr = (const float4*)(W + (size_t)m * CH);
    #pragma unroll 8
    for (int k = 0; k < 64; k++) {
        float4 w = wr[k];
        acc += w.x * ts[4 * k] + w.y * ts[4 * k + 1]
             + w.z * ts[4 * k + 2] + w.w * ts[4 * k + 3];
    }
    g_qb[b * 3 * CH + m] = acc;
}

// ---------------------------------------------------------------------------
// Raw-PTX tf32 channel GEMM (verbatim from passing R13).
// ---------------------------------------------------------------------------
#define G2_LDW 36
#define G2_LDB 136
#define G2_LDE 132
#define G2_WS  (128 * G2_LDW)
#define G2_BS  (32 * G2_LDB)
#define G2_FLOATS (2 * G2_WS + 2 * G2_BS + CH)

template<int MOUT, bool QKV_MODE>
__global__ void __launch_bounds__(256, 2)
gemm_ptx(const float* __restrict__ W, const float* __restrict__ bias,
         const float* __restrict__ inp, const float* __restrict__ resid,
         float* __restrict__ out) {
    extern __shared__ float sm[];
    float* Wbuf = sm;
    float* Bbuf = sm + 2 * G2_WS;
    float* sS   = sm + 2 * G2_WS + 2 * G2_BS;

    int n0 = blockIdx.x * 128;
    int m0 = blockIdx.y * 128;
    int b  = blockIdx.z;
    const float* src = QKV_MODE ? inp : g_att;
    float*       dst = QKV_MODE ? g_qkv : out;
    const float* ib  = src + (size_t)b * CH * NSP;

    int lane = threadIdx.x & 31, warp = threadIdx.x >> 5;
    int g = lane >> 2, t = lane & 3;
    int wm = (warp & 1) * 64;
    int wn = (warp >> 1) * 32;

    if (QKV_MODE && threadIdx.x < 64)
        *(float4*)&sS[threadIdx.x * 4] = *(const float4*)&g_s[b * CH + threadIdx.x * 4];

    float acc[4][4][4];
    #pragma unroll
    for (int mt = 0; mt < 4; mt++)
        #pragma unroll
        for (int nt = 0; nt < 4; nt++)
            #pragma unroll
            for (int c = 0; c < 4; c++) acc[mt][nt][c] = 0.f;

    auto issue = [&](int ch) {
        float* ws = Wbuf + (ch & 1) * G2_WS;
        float* bs = Bbuf + (ch & 1) * G2_BS;
        int k0 = ch * 32;
        #pragma unroll
        for (int idx = threadIdx.x; idx < 1024; idx += 256) {
            int row = idx >> 3, k4 = (idx & 7) * 4;
            __pipeline_memcpy_async(ws + row * G2_LDW + k4,
                W + (size_t)(m0 + row) * CH + k0 + k4, 16);
        }
        #pragma unroll
        for (int idx = threadIdx.x; idx < 1024; idx += 256) {
            int row = idx >> 5, n4 = (idx & 31) * 4;
            __pipeline_memcpy_async(bs + row * G2_LDB + n4,
                ib + (size_t)(k0 + row) * NSP + n0 + n4, 16);
        }
        __pipeline_commit();
    };

    issue(0);
    for (int ch = 0; ch < 8; ch++) {
        float* ws = Wbuf + (ch & 1) * G2_WS;
        float* bs = Bbuf + (ch & 1) * G2_BS;
        __pipeline_wait_prior(0);
        __syncthreads();
        if (ch < 7) issue(ch + 1);
        int k0 = ch * 32;
        #pragma unroll
        for (int k8 = 0; k8 < 4; k8++) {
            int kk = k8 * 8;
            float sv0 = 1.f, sv1 = 1.f;
            if (QKV_MODE) {
                sv0 = sS[k0 + kk + t];
                sv1 = sS[k0 + kk + t + 4];
            }
            uint32_t a[4][4];
            #pragma unroll
            for (int mt = 0; mt < 4; mt++) {
                const float* wr = ws + (wm + mt * 16) * G2_LDW + kk;
                float f0 = wr[g * G2_LDW + t];
                float f1 = wr[(g + 8) * G2_LDW + t];
                float f2 = wr[g * G2_LDW + t + 4];
                float f3 = wr[(g + 8) * G2_LDW + t + 4];
                if (QKV_MODE) { f0 *= sv0; f1 *= sv0; f2 *= sv1; f3 *= sv1; }
                a[mt][0] = __float_as_uint(f0);
                a[mt][1] = __float_as_uint(f1);
                a[mt][2] = __float_as_uint(f2);
                a[mt][3] = __float_as_uint(f3);
            }
            uint32_t bb[4][2];
            #pragma unroll
            for (int nt = 0; nt < 4; nt++) {
                const float* br = bs + kk * G2_LDB + wn + nt * 8 + g;
                bb[nt][0] = __float_as_uint(br[t * G2_LDB]);
                bb[nt][1] = __float_as_uint(br[(t + 4) * G2_LDB]);
            }
            #pragma unroll
            for (int mt = 0; mt < 4; mt++)
                #pragma unroll
                for (int nt = 0; nt < 4; nt++)
                    mma8(acc[mt][nt], a[mt][0], a[mt][1], a[mt][2], a[mt][3],
                         bb[nt][0], bb[nt][1]);
        }
        __syncthreads();
    }

    float* Ss = sm;
    #pragma unroll
    for (int mt = 0; mt < 4; mt++) {
        int r0 = wm + mt * 16 + g;
        #pragma unroll
        for (int nt = 0; nt < 4; nt++) {
            int cc = wn + nt * 8 + 2 * t;
            *(float2*)(Ss + r0 * G2_LDE + cc)       = make_float2(acc[mt][nt][0], acc[mt][nt][1]);
            *(float2*)(Ss + (r0 + 8) * G2_LDE + cc) = make_float2(acc[mt][nt][2], acc[mt][nt][3]);
        }
    }
    __syncthreads();
    for (int idx = threadIdx.x; idx < 4096; idx += 256) {
        int row = idx >> 5, n4 = (idx & 31) * 4;
        int m = m0 + row;
        float4 v = *(float4*)(Ss + row * G2_LDE + n4);
        float bv = QKV_MODE ? g_qb[b * MOUT + m] : bias[m];
        v.x += bv; v.y += bv; v.z += bv; v.w += bv;
        if (!QKV_MODE) {
            float4 rr = *(const float4*)(resid + ((size_t)b * MOUT + m) * NSP + n0 + n4);
            v.x += rr.x; v.y += rr.y; v.z += rr.z; v.w += rr.w;
        }
        *(float4*)(dst + ((size_t)b * MOUT + m) * NSP + n0 + n4) = v;
    }
}

// ---------------------------------------------------------------------------
// Flash attention v4: ldmatrix fragment loads.
// Qt[i][k], Kt[j][d] (transposed), Vs[dc][j], Ps[i][j] — all stride 68
// (conflict-free LDSM row pattern: 68 mod 32 = 4 -> 8 distinct bank quads).
// Per k/j-step: 5 LDSM + 8 mma (was 20 scalar LDS + 8 mma).
// ---------------------------------------------------------------------------
#define ALD 68
#define AQ_OFF 0
#define AK_OFF (128 * ALD)                // 8704
#define AV_OFF (AK_OFF + 64 * ALD)        // 13056
#define AP_OFF (AV_OFF + 64 * ALD)        // 17408
#define AT4_FLOATS (AP_OFF + 128 * ALD)   // 26112 floats -> 104448 B

__global__ void __launch_bounds__(256, 2)
attn_v4() {
    extern __shared__ float sm[];
    float* Qt = sm + AQ_OFF;   // [i 128][k 64]
    float* Kt = sm + AK_OFF;   // [j 64][d 64]
    float* Vs = sm + AV_OFF;   // [dc 64][j 64]
    float* Ps = sm + AP_OFF;   // [i 128][j 64]

    int qt = blockIdx.x, hh = blockIdx.y, b = blockIdx.z;
    const float* qb = g_qkv + ((size_t)b * 3 * CH + hh * 3 * HD) * NSP;
    const float* kb = qb + (size_t)HD * NSP;
    const float* vb = qb + (size_t)2 * HD * NSP;
    int n0 = qt * 128;

    int lane = threadIdx.x & 31, warp = threadIdx.x >> 5;
    int g = lane >> 2, t = lane & 3;
    int iw = warp * 16;
    int idx = threadIdx.x;

    // ldmatrix per-lane addressing:
    // A-frags (Qt/Ps): row = base + r8 + ((mat&1)<<3), col = cb + ((mat>>1)<<2)
    // B-frags (Kt/Vs): row = base + r8 + ((mat>>1)<<3), col = cb + ((mat&1)<<2)
    int r8 = lane & 7, mat = lane >> 3;
    int a_row = r8 + ((mat & 1) << 3);
    int a_col = (mat >> 1) << 2;
    int b_row = r8 + ((mat >> 1) << 3);
    int b_col = (mat & 1) << 2;

    uint32_t qt_u = (uint32_t)__cvta_generic_to_shared(Qt);
    uint32_t kt_u = (uint32_t)__cvta_generic_to_shared(Kt);
    uint32_t vs_u = (uint32_t)__cvta_generic_to_shared(Vs);
    uint32_t ps_u = (uint32_t)__cvta_generic_to_shared(Ps);
    uint32_t qA = qt_u + ((iw + a_row) * ALD + a_col) * 4;
    uint32_t pA = ps_u + ((iw + a_row) * ALD + a_col) * 4;
    uint32_t kB = kt_u + (b_row * ALD + b_col) * 4;
    uint32_t vB = vs_u + (b_row * ALD + b_col) * 4;

    // Load+transpose Q: Qt[i][d] from gmem [d][i]; scale 0.125 folded.
    // Coalesced scalar LDG (warp spans 32 consecutive i), float4 STS.
    {
        int ii = idx & 127;
        int db = (idx >> 7) * 4;
        #pragma unroll
        for (int it = 0; it < 8; it++) {
            int d4 = db + it * 8;
            float x0 = qb[(size_t)(d4 + 0) * NSP + n0 + ii] * 0.125f;
            float x1 = qb[(size_t)(d4 + 1) * NSP + n0 + ii] * 0.125f;
            float x2 = qb[(size_t)(d4 + 2) * NSP + n0 + ii] * 0.125f;
            float x3 = qb[(size_t)(d4 + 3) * NSP + n0 + ii] * 0.125f;
            *(float4*)&Qt[ii * ALD + d4] = make_float4(x0, x1, x2, x3);
        }
    }

    float o[8][4];
    #pragma unroll
    for (int n = 0; n < 8; n++)
        #pragma unroll
        for (int c = 0; c < 4; c++) o[n][c] = 0.f;
    float m0 = -INFINITY, m1 = -INFINITY, l0 = 0.f, l1 = 0.f;

    int kjj = idx & 63;          // K-transpose: row j
    int kdb = (idx >> 6) * 4;    // and d-quad base
    int vdd = idx >> 4;          // V copy: row dc
    int vj4 = (idx & 15) * 4;

    for (int tile = 0; tile < 16; tile++) {
        int j0 = tile * 64;
        // K transpose: Kt[j][d] <- K[d][j0+j] (coalesced LDG, cf float4 STS)
        #pragma unroll
        for (int it = 0; it < 4; it++) {
            int d4 = kdb + it * 16;
            float x0 = kb[(size_t)(d4 + 0) * NSP + j0 + kjj];
            float x1 = kb[(size_t)(d4 + 1) * NSP + j0 + kjj];
            float x2 = kb[(size_t)(d4 + 2) * NSP + j0 + kjj];
            float x3 = kb[(size_t)(d4 + 3) * NSP + j0 + kjj];
            *(float4*)&Kt[kjj * ALD + d4] = make_float4(x0, x1, x2, x3);
        }
        // V direct copy [dc][j]
        #pragma unroll
        for (int it = 0; it < 4; it++) {
            int dd = vdd + it * 16;
            *(float4*)&Vs[dd * ALD + vj4] =
                *(const float4*)(vb + (size_t)dd * NSP + j0 + vj4);
        }
        __syncthreads();

        // S = (Q*scale)^T K via ldmatrix + mma
        float s[8][4];
        #pragma unroll
        for (int n = 0; n < 8; n++)
            #pragma unroll
            for (int c = 0; c < 4; c++) s[n][c] = 0.f;
        #pragma unroll
        for (int k8 = 0; k8 < 8; k8++) {
            int k0 = k8 * 8;
            uint32_t a0, a1, a2, a3;
            ldsm4(a0, a1, a2, a3, qA + k0 * 4);
            #pragma unroll
            for (int np = 0; np < 4; np++) {
                uint32_t b0, b1, b2, b3;
                ldsm4(b0, b1, b2, b3, kB + (np * 16 * ALD + k0) * 4);
                mma8(s[2 * np],     a0, a1, a2, a3, b0, b1);
                mma8(s[2 * np + 1], a0, a1, a2, a3, b2, b3);
            }
        }

        // In-register online softmax (rows iw+g / iw+g+8; reduce over 4 lanes)
        float mx0 = -INFINITY, mx1 = -INFINITY;
        #pragma unroll
        for (int n = 0; n < 8; n++) {
            mx0 = fmaxf(mx0, fmaxf(s[n][0], s[n][1]));
            mx1 = fmaxf(mx1, fmaxf(s[n][2], s[n][3]));
        }
        mx0 = fmaxf(mx0, __shfl_xor_sync(0xffffffffu, mx0, 1));
        mx0 = fmaxf(mx0, __shfl_xor_sync(0xffffffffu, mx0, 2));
        mx1 = fmaxf(mx1, __shfl_xor_sync(0xffffffffu, mx1, 1));
        mx1 = fmaxf(mx1, __shfl_xor_sync(0xffffffffu, mx1, 2));
        float mn0 = fmaxf(m0, mx0), mn1 = fmaxf(m1, mx1);
        float al0 = __expf(m0 - mn0), al1 = __expf(m1 - mn1);
        m0 = mn0; m1 = mn1;
        float r0 = 0.f, r1 = 0.f;
        #pragma unroll
        for (int n = 0; n < 8; n++) {
            s[n][0] = __expf(s[n][0] - mn0);
            s[n][1] = __expf(s[n][1] - mn0);
            s[n][2] = __expf(s[n][2] - mn1);
            s[n][3] = __expf(s[n][3] - mn1);
            r0 += s[n][0] + s[n][1];
            r1 += s[n][2] + s[n][3];
        }
        r0 += __shfl_xor_sync(0xffffffffu, r0, 1);
        r0 += __shfl_xor_sync(0xffffffffu, r0, 2);
        r1 += __shfl_xor_sync(0xffffffffu, r1, 1);
        r1 += __shfl_xor_sync(0xffffffffu, r1, 2);
        l0 = l0 * al0 + r0;
        l1 = l1 * al1 + r1;

        // Store P (warp-private rows; C frag cols 2t,2t+1)
        #pragma unroll
        for (int n = 0; n < 8; n++) {
            *(float2*)(Ps + (iw + g)     * ALD + n * 8 + 2 * t) = make_float2(s[n][0], s[n][1]);
            *(float2*)(Ps + (iw + g + 8) * ALD + n * 8 + 2 * t) = make_float2(s[n][2], s[n][3]);
        }
        __syncwarp();

        // Rescale O
        #pragma unroll
        for (int n = 0; n < 8; n++) {
            o[n][0] *= al0; o[n][1] *= al0;
            o[n][2] *= al1; o[n][3] *= al1;
        }

        // O += P V^T via ldmatrix + mma
        #pragma unroll
        for (int j8 = 0; j8 < 8; j8++) {
            int jj = j8 * 8;
            uint32_t a0, a1, a2, a3;
            ldsm4(a0, a1, a2, a3, pA + jj * 4);
            #pragma unroll
            for (int np = 0; np < 4; np++) {
                uint32_t b0, b1, b2, b3;
                ldsm4(b0, b1, b2, b3, vB + (np * 16 * ALD + jj) * 4);
                mma8(o[2 * np],     a0, a1, a2, a3, b0, b1);
                mma8(o[2 * np + 1], a0, a1, a2, a3, b2, b3);
            }
        }
        __syncthreads();   // all warps done with Kt/Vs before next tile load
    }

    // Normalize, stage transposed [dc][i] in P region, coalesced store
    float inv0 = 1.f / l0, inv1 = 1.f / l1;
    #pragma unroll
    for (int n = 0; n < 8; n++) {
        o[n][0] *= inv0; o[n][1] *= inv0;
        o[n][2] *= inv1; o[n][3] *= inv1;
    }
    float* Os = sm + AP_OFF;   // 64 x 132 = 8448 <= 8704
    #pragma unroll
    for (int n = 0; n < 8; n++) {
        int dc = n * 8 + 2 * t;
        Os[dc * 132 + iw + g]           = o[n][0];
        Os[(dc + 1) * 132 + iw + g]     = o[n][1];
        Os[dc * 132 + iw + g + 8]       = o[n][2];
        Os[(dc + 1) * 132 + iw + g + 8] = o[n][3];
    }
    __syncthreads();
    float* ob = g_att + ((size_t)b * CH + hh * HD) * NSP + n0;
    for (int i2 = threadIdx.x; i2 < 2048; i2 += 256) {
        int dc = i2 >> 5, i4 = (i2 & 31) * 4;
        *(float4*)(ob + (size_t)dc * NSP + i4) = *(float4*)(Os + dc * 132 + i4);
    }
}

// ---------------------------------------------------------------------------

extern "C" void kernel_launch(void* const* d_in, const int* in_sizes, int n_in,
                              void* d_out, int out_size) {
    const float* x      = (const float*)d_in[0];
    const float* gamma  = (const float*)d_in[1];
    const float* beta   = (const float*)d_in[2];
    const float* qkv_w  = (const float*)d_in[3];
    const float* qkv_b  = (const float*)d_in[4];
    const float* proj_w = (const float*)d_in[5];
    const float* proj_b = (const float*)d_in[6];
    float* out = (float*)d_out;

    const int gm_smem  = G2_FLOATS * 4;
    const int att_smem = AT4_FLOATS * 4;

    cudaFuncSetAttribute(gemm_ptx<768, true>,
                         cudaFuncAttributeMaxDynamicSharedMemorySize, gm_smem);
    cudaFuncSetAttribute(gemm_ptx<256, false>,
                         cudaFuncAttributeMaxDynamicSharedMemorySize, gm_smem);
    cudaFuncSetAttribute(attn_v4,
                         cudaFuncAttributeMaxDynamicSharedMemorySize, att_smem);

    gn_stats<<<BATCH * NGRP, 256>>>(x, gamma, beta);
    qkv_bias_kernel<<<dim3(6, BATCH), 128>>>(qkv_w, qkv_b);
    gemm_ptx<768, true ><<<dim3(8, 6, BATCH), 256, gm_smem>>>(qkv_w, qkv_b /*unused*/, x, x /*unused*/, out /*unused*/);
    attn_v4<<<dim3(NSP / 128, NHEADS, BATCH), 256, att_smem>>>();
    gemm_ptx<256, false><<<dim3(8, 2, BATCH), 256, gm_smem>>>(proj_w, proj_b, x /*unused*/, x, out);
}

// round 16
// speedup vs baseline: 1.5367x; 1.0864x over previous
#include <cuda_runtime.h>
#include <cuda_pipeline.h>
#include <math.h>
#include <stdint.h>

#define BATCH  16
#define CH     256
#define NSP    1024      // H*W
#define NHEADS 4
#define HD     64
#define NGRP   32
#define CPG    8

// Scratch (allocation-free: __device__ globals)
__device__ float g_qkv [BATCH * 3 * CH * NSP];   // qkv (V rows used, interleaved layout)
__device__ float g_qkT [BATCH * 8 * NSP * HD];   // slots 0-3: Q^T per head (x0.125), 4-7: K^T
__device__ float g_att [BATCH * CH * NSP];       // attention output
__device__ float g_s   [BATCH * CH];             // GN scale  (gamma*rstd)
__device__ float g_t   [BATCH * CH];             // GN shift  (beta - mu*scale)
__device__ float g_qb  [BATCH * 3 * CH];         // fused qkv bias: qkv_b + W*t

// ---------------------------------------------------------------------------
// m16n8k8 tf32 mma (raw fp32 bits in, fp32 accum) + ldmatrix x4
// ---------------------------------------------------------------------------
__device__ __forceinline__ void mma8(float d[4],
    uint32_t a0, uint32_t a1, uint32_t a2, uint32_t a3,
    uint32_t b0, uint32_t b1) {
    asm volatile(
        "mma.sync.aligned.m16n8k8.row.col.f32.tf32.tf32.f32 "
        "{%0,%1,%2,%3}, {%4,%5,%6,%7}, {%8,%9}, {%0,%1,%2,%3};\n"
        : "+f"(d[0]), "+f"(d[1]), "+f"(d[2]), "+f"(d[3])
        : "r"(a0), "r"(a1), "r"(a2), "r"(a3), "r"(b0), "r"(b1));
}

__device__ __forceinline__ void ldsm4(uint32_t& r0, uint32_t& r1,
                                      uint32_t& r2, uint32_t& r3, uint32_t a) {
    asm volatile("ldmatrix.sync.aligned.m8n8.x4.shared.b16 {%0,%1,%2,%3}, [%4];"
        : "=r"(r0), "=r"(r1), "=r"(r2), "=r"(r3) : "r"(a));
}

// ---------------------------------------------------------------------------
// GN statistics only
// ---------------------------------------------------------------------------
__global__ void __launch_bounds__(256)
gn_stats(const float* __restrict__ x,
         const float* __restrict__ gamma,
         const float* __restrict__ beta) {
    int b = blockIdx.x >> 5;
    int g = blockIdx.x & 31;
    const float4* xb = (const float4*)(x + ((size_t)b * CH + g * CPG) * NSP);

    float s = 0.f, s2 = 0.f;
    for (int i = threadIdx.x; i < 2048; i += 256) {
        float4 v = xb[i];
        s  += v.x + v.y + v.z + v.w;
        s2 += v.x * v.x + v.y * v.y + v.z * v.z + v.w * v.w;
    }
    __shared__ float rs[256], rq[256];
    rs[threadIdx.x] = s; rq[threadIdx.x] = s2;
    __syncthreads();
    for (int o = 128; o > 0; o >>= 1) {
        if (threadIdx.x < o) {
            rs[threadIdx.x] += rs[threadIdx.x + o];
            rq[threadIdx.x] += rq[threadIdx.x + o];
        }
        __syncthreads();
    }
    if (threadIdx.x < CPG) {
        float mu   = rs[0] * (1.f / 8192.f);
        float var  = rq[0] * (1.f / 8192.f) - mu * mu;
        float rstd = rsqrtf(var + 1e-5f);
        int c = g * CPG + threadIdx.x;
        float sv = gamma[c] * rstd;
        g_s[b * CH + c] = sv;
        g_t[b * CH + c] = beta[c] - mu * sv;
    }
}

// ---------------------------------------------------------------------------
// Fused qkv bias: g_qb[b][m] = qkv_b[m] + sum_k W[m,k]*g_t[b,k]
// ---------------------------------------------------------------------------
__global__ void __launch_bounds__(128)
qkv_bias_kernel(const float* __restrict__ W, const float* __restrict__ qkv_b) {
    int b = blockIdx.y;
    int m = blockIdx.x * 128 + threadIdx.x;
    __shared__ float ts[CH];
    if (threadIdx.x < 64)
        *(float4*)&ts[threadIdx.x * 4] = *(const float4*)&g_t[b * CH + threadIdx.x * 4];
    __syncthreads();
    float acc = qkv_b[m];
    const float4* wr = (const float4*)(W + (size_t)m * CH);
    #pragma unroll 8
    for (int k = 0; k < 64; k++) {
        float4 w = wr[k];
        acc += w.x * ts[4 * k] + w.y * ts[4 * k + 1]
             + w.z * ts[4 * k + 2] + w.w * ts[4 * k + 3];
    }
    g_qb[b * 3 * CH + m] = acc;
}

// ---------------------------------------------------------------------------
// Raw-PTX tf32 channel GEMM with CHUNK REMAP in QKV mode.
// qkv rows are head-interleaved: chunk c (64 rows) has head=c/3, type=c%3
// (0=Q,1=K,2=V). Block y handles chunks {typ+6*pair, typ+6*pair+3} with
// typ=y>>1, pair=y&1 -> each block is type-uniform. Q/K blocks store
// transposed to g_qkT (Q scaled 0.125); V blocks store normally to g_qkv.
// Proj mode unchanged (contiguous m).
// ---------------------------------------------------------------------------
#define G2_LDW 36
#define G2_LDB 136
#define G2_LDE 132
#define G2_WS  (128 * G2_LDW)
#define G2_BS  (32 * G2_LDB)
#define G2_FLOATS (2 * G2_WS + 2 * G2_BS + CH)

template<int MOUT, bool QKV_MODE>
__global__ void __launch_bounds__(256, 2)
gemm_ptx(const float* __restrict__ W, const float* __restrict__ bias,
         const float* __restrict__ inp, const float* __restrict__ resid,
         float* __restrict__ out) {
    extern __shared__ float sm[];
    float* Wbuf = sm;
    float* Bbuf = sm + 2 * G2_WS;
    float* sS   = sm + 2 * G2_WS + 2 * G2_BS;

    int n0 = blockIdx.x * 128;
    int b  = blockIdx.z;
    int typ = 0, pair = 0, mA, mB;
    if (QKV_MODE) {
        typ  = blockIdx.y >> 1;
        pair = blockIdx.y & 1;
        mA = (typ + pair * 6) * 64;       // first chunk's row base
        mB = (typ + pair * 6 + 3) * 64;   // second chunk's row base
    } else {
        mA = blockIdx.y * 128;
        mB = mA + 64;
    }
    const float* src = QKV_MODE ? inp : g_att;
    float*       dst = QKV_MODE ? g_qkv : out;
    const float* ib  = src + (size_t)b * CH * NSP;

    int lane = threadIdx.x & 31, warp = threadIdx.x >> 5;
    int g = lane >> 2, t = lane & 3;
    int wm = (warp & 1) * 64;
    int wn = (warp >> 1) * 32;

    if (QKV_MODE && threadIdx.x < 64)
        *(float4*)&sS[threadIdx.x * 4] = *(const float4*)&g_s[b * CH + threadIdx.x * 4];

    float acc[4][4][4];
    #pragma unroll
    for (int mt = 0; mt < 4; mt++)
        #pragma unroll
        for (int nt = 0; nt < 4; nt++)
            #pragma unroll
            for (int c = 0; c < 4; c++) acc[mt][nt][c] = 0.f;

    auto issue = [&](int ch) {
        float* ws = Wbuf + (ch & 1) * G2_WS;
        float* bs = Bbuf + (ch & 1) * G2_BS;
        int k0 = ch * 32;
        #pragma unroll
        for (int idx = threadIdx.x; idx < 1024; idx += 256) {
            int row = idx >> 3, k4 = (idx & 7) * 4;
            int m = (row < 64) ? (mA + row) : (mB + row - 64);
            __pipeline_memcpy_async(ws + row * G2_LDW + k4,
                W + (size_t)m * CH + k0 + k4, 16);
        }
        #pragma unroll
        for (int idx = threadIdx.x; idx < 1024; idx += 256) {
            int row = idx >> 5, n4 = (idx & 31) * 4;
            __pipeline_memcpy_async(bs + row * G2_LDB + n4,
                ib + (size_t)(k0 + row) * NSP + n0 + n4, 16);
        }
        __pipeline_commit();
    };

    issue(0);
    for (int ch = 0; ch < 8; ch++) {
        float* ws = Wbuf + (ch & 1) * G2_WS;
        float* bs = Bbuf + (ch & 1) * G2_BS;
        __pipeline_wait_prior(0);
        __syncthreads();
        if (ch < 7) issue(ch + 1);
        int k0 = ch * 32;
        #pragma unroll
        for (int k8 = 0; k8 < 4; k8++) {
            int kk = k8 * 8;
            float sv0 = 1.f, sv1 = 1.f;
            if (QKV_MODE) {
                sv0 = sS[k0 + kk + t];
                sv1 = sS[k0 + kk + t + 4];
            }
            uint32_t a[4][4];
            #pragma unroll
            for (int mt = 0; mt < 4; mt++) {
                const float* wr = ws + (wm + mt * 16) * G2_LDW + kk;
                float f0 = wr[g * G2_LDW + t];
                float f1 = wr[(g + 8) * G2_LDW + t];
                float f2 = wr[g * G2_LDW + t + 4];
                float f3 = wr[(g + 8) * G2_LDW + t + 4];
                if (QKV_MODE) { f0 *= sv0; f1 *= sv0; f2 *= sv1; f3 *= sv1; }
                a[mt][0] = __float_as_uint(f0);
                a[mt][1] = __float_as_uint(f1);
                a[mt][2] = __float_as_uint(f2);
                a[mt][3] = __float_as_uint(f3);
            }
            uint32_t bb[4][2];
            #pragma unroll
            for (int nt = 0; nt < 4; nt++) {
                const float* br = bs + kk * G2_LDB + wn + nt * 8 + g;
                bb[nt][0] = __float_as_uint(br[t * G2_LDB]);
                bb[nt][1] = __float_as_uint(br[(t + 4) * G2_LDB]);
            }
            #pragma unroll
            for (int mt = 0; mt < 4; mt++)
                #pragma unroll
                for (int nt = 0; nt < 4; nt++)
                    mma8(acc[mt][nt], a[mt][0], a[mt][1], a[mt][2], a[mt][3],
                         bb[nt][0], bb[nt][1]);
        }
        __syncthreads();
    }

    if (QKV_MODE && typ < 2) {
        // ---- transposed epilogue: Q/K chunks -> g_qkT[b][head+4*typ][n][d] ----
        float* St = sm;   // [n 128][rloc 128] pad 132 = 16896 <= 17920
        #pragma unroll
        for (int mt = 0; mt < 4; mt++) {
            int r0 = wm + mt * 16 + g;
            #pragma unroll
            for (int nt = 0; nt < 4; nt++) {
                int cc = wn + nt * 8 + 2 * t;
                St[cc * 132 + r0]           = acc[mt][nt][0];
                St[(cc + 1) * 132 + r0]     = acc[mt][nt][1];
                St[cc * 132 + r0 + 8]       = acc[mt][nt][2];
                St[(cc + 1) * 132 + r0 + 8] = acc[mt][nt][3];
            }
        }
        __syncthreads();
        float qs = (typ == 0) ? 0.125f : 1.f;   // fold softmax scale into Q
        int dl = (threadIdx.x & 15) * 4;        // d-quad within head
        int nb = threadIdx.x >> 4;              // n base 0..15
        #pragma unroll
        for (int h2 = 0; h2 < 2; h2++) {
            int chunk = typ + pair * 6 + h2 * 3;
            int head  = pair * 2 + h2;
            int slot  = head + (typ == 1 ? 4 : 0);
            int mloc  = h2 * 64 + dl;
            float4 bv = *(const float4*)&g_qb[b * 768 + chunk * 64 + dl];
            float* ob = g_qkT + ((size_t)b * 8 + slot) * NSP * HD;
            #pragma unroll
            for (int it = 0; it < 8; it++) {
                int n = nb + it * 16;
                float4 v = *(float4*)&St[n * 132 + mloc];
                v.x = (v.x + bv.x) * qs; v.y = (v.y + bv.y) * qs;
                v.z = (v.z + bv.z) * qs; v.w = (v.w + bv.w) * qs;
                *(float4*)(ob + (size_t)(n0 + n) * HD + dl) = v;
            }
        }
    } else {
        // ---- normal epilogue (V chunks / proj) ----
        float* Ss = sm;
        #pragma unroll
        for (int mt = 0; mt < 4; mt++) {
            int r0 = wm + mt * 16 + g;
            #pragma unroll
            for (int nt = 0; nt < 4; nt++) {
                int cc = wn + nt * 8 + 2 * t;
                *(float2*)(Ss + r0 * G2_LDE + cc)       = make_float2(acc[mt][nt][0], acc[mt][nt][1]);
                *(float2*)(Ss + (r0 + 8) * G2_LDE + cc) = make_float2(acc[mt][nt][2], acc[mt][nt][3]);
            }
        }
        __syncthreads();
        for (int idx = threadIdx.x; idx < 4096; idx += 256) {
            int row = idx >> 5, n4 = (idx & 31) * 4;
            int m = (row < 64) ? (mA + row) : (mB + row - 64);
            float4 v = *(float4*)(Ss + row * G2_LDE + n4);
            float bv = QKV_MODE ? g_qb[b * 768 + m] : bias[m];
            v.x += bv; v.y += bv; v.z += bv; v.w += bv;
            if (!QKV_MODE) {
                float4 rr = *(const float4*)(resid + ((size_t)b * MOUT + m) * NSP + n0 + n4);
                v.x += rr.x; v.y += rr.y; v.z += rr.z; v.w += rr.w;
            }
            *(float4*)(dst + ((size_t)b * MOUT + m) * NSP + n0 + n4) = v;
        }
    }
}

// ---------------------------------------------------------------------------
// Flash attention v5: Q fragments register-resident (loaded once via LDSM);
// K/V cp.async double-buffered (pre-transposed K from g_qkT, interleaved V
// rows from g_qkv); P through warp-private smem. 2 barriers/tile.
// ---------------------------------------------------------------------------
#define ALD 68
#define KBUF (64 * ALD)                   // 4352
#define AK_OFF 0                          // two K bufs
#define AV_OFF (2 * KBUF)                 // two V bufs
#define AP_OFF (4 * KBUF)                 // P [i 128][j 64] (Q staged here 1st)
#define AT5_FLOATS (AP_OFF + 128 * ALD)   // 26112 floats -> 104448 B

__global__ void __launch_bounds__(256, 2)
attn_v5() {
    extern __shared__ float sm[];
    float* Ps = sm + AP_OFF;

    int qt = blockIdx.x, hh = blockIdx.y, b = blockIdx.z;
    const float* qTb = g_qkT + ((size_t)b * 8 + hh) * NSP * HD;       // Q^T (x0.125)
    const float* kTb = g_qkT + ((size_t)b * 8 + 4 + hh) * NSP * HD;   // K^T
    const float* vb  = g_qkv + ((size_t)b * 768 + hh * 192 + 128) * NSP; // interleaved V
    int n0 = qt * 128;

    int lane = threadIdx.x & 31, warp = threadIdx.x >> 5;
    int g = lane >> 2, t = lane & 3;
    int iw = warp * 16;
    int idx = threadIdx.x;

    int r8 = lane & 7, mat = lane >> 3;
    int a_row = r8 + ((mat & 1) << 3);
    int a_col = (mat >> 1) << 2;
    int b_row = r8 + ((mat >> 1) << 3);
    int b_col = (mat & 1) << 2;

    uint32_t sm_u = (uint32_t)__cvta_generic_to_shared(sm);
    uint32_t pA = sm_u + (AP_OFF + (iw + a_row) * ALD + a_col) * 4;
    uint32_t kB0 = sm_u + (AK_OFF + b_row * ALD + b_col) * 4;
    uint32_t vB0 = sm_u + (AV_OFF + b_row * ALD + b_col) * 4;

    auto issue = [&](int tile) {
        float* kd = sm + AK_OFF + (tile & 1) * KBUF;
        float* vd = sm + AV_OFF + (tile & 1) * KBUF;
        int j0 = tile * 64;
        #pragma unroll
        for (int i2 = idx; i2 < 1024; i2 += 256) {
            int r = i2 >> 4, c = (i2 & 15) * 4;
            __pipeline_memcpy_async(kd + r * ALD + c,
                kTb + (size_t)(j0 + r) * HD + c, 16);
            __pipeline_memcpy_async(vd + r * ALD + c,
                vb + (size_t)r * NSP + j0 + c, 16);
        }
        __pipeline_commit();
    };

    // Prologue: stage Q (pre-scaled, pre-transposed) into P region; K/V 0,1
    #pragma unroll
    for (int i2 = idx; i2 < 2048; i2 += 256) {
        int r = i2 >> 4, c = (i2 & 15) * 4;
        __pipeline_memcpy_async(Ps + r * ALD + c,
            qTb + (size_t)(n0 + r) * HD + c, 16);
    }
    __pipeline_commit();
    issue(0);
    issue(1);
    __pipeline_wait_prior(0);
    __syncthreads();

    // Hoist Q fragments into registers, then P may reuse the region
    uint32_t qa[8][4];
    #pragma unroll
    for (int k8 = 0; k8 < 8; k8++)
        ldsm4(qa[k8][0], qa[k8][1], qa[k8][2], qa[k8][3], pA + k8 * 32);

    float o[8][4];
    #pragma unroll
    for (int n = 0; n < 8; n++)
        #pragma unroll
        for (int c = 0; c < 4; c++) o[n][c] = 0.f;
    float m0 = -INFINITY, m1 = -INFINITY, l0 = 0.f, l1 = 0.f;

    for (int tile = 0; tile < 16; tile++) {
        __pipeline_wait_prior(1);
        __syncthreads();
        uint32_t bufo = (tile & 1) * KBUF * 4;
        uint32_t kB = kB0 + bufo;
        uint32_t vB = vB0 + bufo;

        // S = Q^T K (Q frags in regs; K via LDSM)
        float s[8][4];
        #pragma unroll
        for (int n = 0; n < 8; n++)
            #pragma unroll
            for (int c = 0; c < 4; c++) s[n][c] = 0.f;
        #pragma unroll
        for (int k8 = 0; k8 < 8; k8++) {
            int k0 = k8 * 8;
            #pragma unroll
            for (int np = 0; np < 4; np++) {
                uint32_t b0, b1, b2, b3;
                ldsm4(b0, b1, b2, b3, kB + (np * 16 * ALD + k0) * 4);
                mma8(s[2 * np],     qa[k8][0], qa[k8][1], qa[k8][2], qa[k8][3], b0, b1);
                mma8(s[2 * np + 1], qa[k8][0], qa[k8][1], qa[k8][2], qa[k8][3], b2, b3);
            }
        }

        // In-register online softmax
        float mx0 = -INFINITY, mx1 = -INFINITY;
        #pragma unroll
        for (int n = 0; n < 8; n++) {
            mx0 = fmaxf(mx0, fmaxf(s[n][0], s[n][1]));
            mx1 = fmaxf(mx1, fmaxf(s[n][2], s[n][3]));
        }
        mx0 = fmaxf(mx0, __shfl_xor_sync(0xffffffffu, mx0, 1));
        mx0 = fmaxf(mx0, __shfl_xor_sync(0xffffffffu, mx0, 2));
        mx1 = fmaxf(mx1, __shfl_xor_sync(0xffffffffu, mx1, 1));
        mx1 = fmaxf(mx1, __shfl_xor_sync(0xffffffffu, mx1, 2));
        float mn0 = fmaxf(m0, mx0), mn1 = fmaxf(m1, mx1);
        float al0 = __expf(m0 - mn0), al1 = __expf(m1 - mn1);
        m0 = mn0; m1 = mn1;
        float r0 = 0.f, r1 = 0.f;
        #pragma unroll
        for (int n = 0; n < 8; n++) {
            s[n][0] = __expf(s[n][0] - mn0);
            s[n][1] = __expf(s[n][1] - mn0);
            s[n][2] = __expf(s[n][2] - mn1);
            s[n][3] = __expf(s[n][3] - mn1);
            r0 += s[n][0] + s[n][1];
            r1 += s[n][2] + s[n][3];
        }
        r0 += __shfl_xor_sync(0xffffffffu, r0, 1);
        r0 += __shfl_xor_sync(0xffffffffu, r0, 2);
        r1 += __shfl_xor_sync(0xffffffffu, r1, 1);
        r1 += __shfl_xor_sync(0xffffffffu, r1, 2);
        l0 = l0 * al0 + r0;
        l1 = l1 * al1 + r1;

        // Store P (warp-private rows)
        #pragma unroll
        for (int n = 0; n < 8; n++) {
            *(float2*)(Ps + (iw + g)     * ALD + n * 8 + 2 * t) = make_float2(s[n][0], s[n][1]);
            *(float2*)(Ps + (iw + g + 8) * ALD + n * 8 + 2 * t) = make_float2(s[n][2], s[n][3]);
        }
        __syncwarp();

        // Rescale O
        #pragma unroll
        for (int n = 0; n < 8; n++) {
            o[n][0] *= al0; o[n][1] *= al0;
            o[n][2] *= al1; o[n][3] *= al1;
        }

        // O += P V^T via LDSM + mma
        #pragma unroll
        for (int j8 = 0; j8 < 8; j8++) {
            int jj = j8 * 8;
            uint32_t a0, a1, a2, a3;
            ldsm4(a0, a1, a2, a3, pA + jj * 4);
            #pragma unroll
            for (int np = 0; np < 4; np++) {
                uint32_t b0, b1, b2, b3;
                ldsm4(b0, b1, b2, b3, vB + (np * 16 * ALD + jj) * 4);
                mma8(o[2 * np],     a0, a1, a2, a3, b0, b1);
                mma8(o[2 * np + 1], a0, a1, a2, a3, b2, b3);
            }
        }
        __syncthreads();          // all warps done with buf (tile&1)
        if (tile < 14) issue(tile + 2);
    }

    // Normalize, stage transposed [dc][i] in P region, coalesced store
    float inv0 = 1.f / l0, inv1 = 1.f / l1;
    #pragma unroll
    for (int n = 0; n < 8; n++) {
        o[n][0] *= inv0; o[n][1] *= inv0;
        o[n][2] *= inv1; o[n][3] *= inv1;
    }
    float* Os = sm + AP_OFF;   // 64 x 132 = 8448 <= 8704
    #pragma unroll
    for (int n = 0; n < 8; n++) {
        int dc = n * 8 + 2 * t;
        Os[dc * 132 + iw + g]           = o[n][0];
        Os[(dc + 1) * 132 + iw + g]     = o[n][1];
        Os[dc * 132 + iw + g + 8]       = o[n][2];
        Os[(dc + 1) * 132 + iw + g + 8] = o[n][3];
    }
    __syncthreads();
    float* ob = g_att + ((size_t)b * CH + hh * HD) * NSP + n0;
    for (int i2 = threadIdx.x; i2 < 2048; i2 += 256) {
        int dc = i2 >> 5, i4 = (i2 & 31) * 4;
        *(float4*)(ob + (size_t)dc * NSP + i4) = *(float4*)(Os + dc * 132 + i4);
    }
}

// ---------------------------------------------------------------------------

extern "C" void kernel_launch(void* const* d_in, const int* in_sizes, int n_in,
                              void* d_out, int out_size) {
    const float* x      = (const float*)d_in[0];
    const float* gamma  = (const float*)d_in[1];
    const float* beta   = (const float*)d_in[2];
    const float* qkv_w  = (const float*)d_in[3];
    const float* qkv_b  = (const float*)d_in[4];
    const float* proj_w = (const float*)d_in[5];
    const float* proj_b = (const float*)d_in[6];
    float* out = (float*)d_out;

    const int gm_smem  = G2_FLOATS * 4;
    const int att_smem = AT5_FLOATS * 4;

    cudaFuncSetAttribute(gemm_ptx<768, true>,
                         cudaFuncAttributeMaxDynamicSharedMemorySize, gm_smem);
    cudaFuncSetAttribute(gemm_ptx<256, false>,
                         cudaFuncAttributeMaxDynamicSharedMemorySize, gm_smem);
    cudaFuncSetAttribute(attn_v5,
                         cudaFuncAttributeMaxDynamicSharedMemorySize, att_smem);

    gn_stats<<<BATCH * NGRP, 256>>>(x, gamma, beta);
    qkv_bias_kernel<<<dim3(6, BATCH), 128>>>(qkv_w, qkv_b);
    gemm_ptx<768, true ><<<dim3(8, 6, BATCH), 256, gm_smem>>>(qkv_w, qkv_b /*unused*/, x, x /*unused*/, out /*unused*/);
    attn_v5<<<dim3(NSP / 128, NHEADS, BATCH), 256, att_smem>>>();
    gemm_ptx<256, false><<<dim3(8, 2, BATCH), 256, gm_smem>>>(proj_w, proj_b, x /*unused*/, x, out);
}

// round 17
// speedup vs baseline: 2.0935x; 1.3623x over previous
#include <cuda_runtime.h>
#include <cuda_pipeline.h>
#include <cuda_bf16.h>
#include <math.h>
#include <stdint.h>

#define BATCH  16
#define CH     256
#define NSP    1024      // H*W
#define NHEADS 4
#define HD     64
#define NGRP   32
#define CPG    8

// Scratch (allocation-free: __device__ globals)
__device__ __nv_bfloat16 g_qkT[BATCH * 8 * NSP * HD];  // 0-3: Q^T(x0.125), 4-7: K^T
__device__ __nv_bfloat16 g_vT [BATCH * 4 * NSP * HD];  // V: [b][h][dc][n]
__device__ float g_att [BATCH * CH * NSP];             // attention output (fp32)
__device__ float g_s   [BATCH * CH];                   // GN scale
__device__ float g_t   [BATCH * CH];                   // GN shift
__device__ float g_qb  [BATCH * 3 * CH];               // fused qkv bias

// ---------------------------------------------------------------------------
// mma helpers
// ---------------------------------------------------------------------------
__device__ __forceinline__ void mma8(float d[4],
    uint32_t a0, uint32_t a1, uint32_t a2, uint32_t a3,
    uint32_t b0, uint32_t b1) {
    asm volatile(
        "mma.sync.aligned.m16n8k8.row.col.f32.tf32.tf32.f32 "
        "{%0,%1,%2,%3}, {%4,%5,%6,%7}, {%8,%9}, {%0,%1,%2,%3};\n"
        : "+f"(d[0]), "+f"(d[1]), "+f"(d[2]), "+f"(d[3])
        : "r"(a0), "r"(a1), "r"(a2), "r"(a3), "r"(b0), "r"(b1));
}

__device__ __forceinline__ void mmabf(float d[4],
    uint32_t a0, uint32_t a1, uint32_t a2, uint32_t a3,
    uint32_t b0, uint32_t b1) {
    asm volatile(
        "mma.sync.aligned.m16n8k16.row.col.f32.bf16.bf16.f32 "
        "{%0,%1,%2,%3}, {%4,%5,%6,%7}, {%8,%9}, {%0,%1,%2,%3};\n"
        : "+f"(d[0]), "+f"(d[1]), "+f"(d[2]), "+f"(d[3])
        : "r"(a0), "r"(a1), "r"(a2), "r"(a3), "r"(b0), "r"(b1));
}

__device__ __forceinline__ void ldsm4(uint32_t& r0, uint32_t& r1,
                                      uint32_t& r2, uint32_t& r3, uint32_t a) {
    asm volatile("ldmatrix.sync.aligned.m8n8.x4.shared.b16 {%0,%1,%2,%3}, [%4];"
        : "=r"(r0), "=r"(r1), "=r"(r2), "=r"(r3) : "r"(a));
}

// ---------------------------------------------------------------------------
// GN statistics only
// ---------------------------------------------------------------------------
__global__ void __launch_bounds__(256)
gn_stats(const float* __restrict__ x,
         const float* __restrict__ gamma,
         const float* __restrict__ beta) {
    int b = blockIdx.x >> 5;
    int g = blockIdx.x & 31;
    const float4* xb = (const float4*)(x + ((size_t)b * CH + g * CPG) * NSP);

    float s = 0.f, s2 = 0.f;
    for (int i = threadIdx.x; i < 2048; i += 256) {
        float4 v = xb[i];
        s  += v.x + v.y + v.z + v.w;
        s2 += v.x * v.x + v.y * v.y + v.z * v.z + v.w * v.w;
    }
    __shared__ float rs[256], rq[256];
    rs[threadIdx.x] = s; rq[threadIdx.x] = s2;
    __syncthreads();
    for (int o = 128; o > 0; o >>= 1) {
        if (threadIdx.x < o) {
            rs[threadIdx.x] += rs[threadIdx.x + o];
            rq[threadIdx.x] += rq[threadIdx.x + o];
        }
        __syncthreads();
    }
    if (threadIdx.x < CPG) {
        float mu   = rs[0] * (1.f / 8192.f);
        float var  = rq[0] * (1.f / 8192.f) - mu * mu;
        float rstd = rsqrtf(var + 1e-5f);
        int c = g * CPG + threadIdx.x;
        float sv = gamma[c] * rstd;
        g_s[b * CH + c] = sv;
        g_t[b * CH + c] = beta[c] - mu * sv;
    }
}

// ---------------------------------------------------------------------------
// Fused qkv bias
// ---------------------------------------------------------------------------
__global__ void __launch_bounds__(128)
qkv_bias_kernel(const float* __restrict__ W, const float* __restrict__ qkv_b) {
    int b = blockIdx.y;
    int m = blockIdx.x * 128 + threadIdx.x;
    __shared__ float ts[CH];
    if (threadIdx.x < 64)
        *(float4*)&ts[threadIdx.x * 4] = *(const float4*)&g_t[b * CH + threadIdx.x * 4];
    __syncthreads();
    float acc = qkv_b[m];
    const float4* wr = (const float4*)(W + (size_t)m * CH);
    #pragma unroll 8
    for (int k = 0; k < 64; k++) {
        float4 w = wr[k];
        acc += w.x * ts[4 * k] + w.y * ts[4 * k + 1]
             + w.z * ts[4 * k + 2] + w.w * ts[4 * k + 3];
    }
    g_qb[b * 3 * CH + m] = acc;
}

// ---------------------------------------------------------------------------
// tf32 GEMM with chunk remap (QKV) — epilogues now store bf16 for Q/K/V.
// Proj mode unchanged (fp32 + residual).
// ---------------------------------------------------------------------------
#define G2_LDW 36
#define G2_LDB 136
#define G2_LDE 132
#define G2_WS  (128 * G2_LDW)
#define G2_BS  (32 * G2_LDB)
#define G2_FLOATS (2 * G2_WS + 2 * G2_BS + CH)

template<int MOUT, bool QKV_MODE>
__global__ void __launch_bounds__(256, 2)
gemm_ptx(const float* __restrict__ W, const float* __restrict__ bias,
         const float* __restrict__ inp, const float* __restrict__ resid,
         float* __restrict__ out) {
    extern __shared__ float sm[];
    float* Wbuf = sm;
    float* Bbuf = sm + 2 * G2_WS;
    float* sS   = sm + 2 * G2_WS + 2 * G2_BS;

    int n0 = blockIdx.x * 128;
    int b  = blockIdx.z;
    int typ = 0, pair = 0, mA, mB;
    if (QKV_MODE) {
        typ  = blockIdx.y >> 1;
        pair = blockIdx.y & 1;
        mA = (typ + pair * 6) * 64;
        mB = (typ + pair * 6 + 3) * 64;
    } else {
        mA = blockIdx.y * 128;
        mB = mA + 64;
    }
    const float* src = QKV_MODE ? inp : g_att;
    const float* ib  = src + (size_t)b * CH * NSP;

    int lane = threadIdx.x & 31, warp = threadIdx.x >> 5;
    int g = lane >> 2, t = lane & 3;
    int wm = (warp & 1) * 64;
    int wn = (warp >> 1) * 32;

    if (QKV_MODE && threadIdx.x < 64)
        *(float4*)&sS[threadIdx.x * 4] = *(const float4*)&g_s[b * CH + threadIdx.x * 4];

    float acc[4][4][4];
    #pragma unroll
    for (int mt = 0; mt < 4; mt++)
        #pragma unroll
        for (int nt = 0; nt < 4; nt++)
            #pragma unroll
            for (int c = 0; c < 4; c++) acc[mt][nt][c] = 0.f;

    auto issue = [&](int ch) {
        float* ws = Wbuf + (ch & 1) * G2_WS;
        float* bs = Bbuf + (ch & 1) * G2_BS;
        int k0 = ch * 32;
        #pragma unroll
        for (int idx = threadIdx.x; idx < 1024; idx += 256) {
            int row = idx >> 3, k4 = (idx & 7) * 4;
            int m = (row < 64) ? (mA + row) : (mB + row - 64);
            __pipeline_memcpy_async(ws + row * G2_LDW + k4,
                W + (size_t)m * CH + k0 + k4, 16);
        }
        #pragma unroll
        for (int idx = threadIdx.x; idx < 1024; idx += 256) {
            int row = idx >> 5, n4 = (idx & 31) * 4;
            __pipeline_memcpy_async(bs + row * G2_LDB + n4,
                ib + (size_t)(k0 + row) * NSP + n0 + n4, 16);
        }
        __pipeline_commit();
    };

    issue(0);
    for (int ch = 0; ch < 8; ch++) {
        float* ws = Wbuf + (ch & 1) * G2_WS;
        float* bs = Bbuf + (ch & 1) * G2_BS;
        __pipeline_wait_prior(0);
        __syncthreads();
        if (ch < 7) issue(ch + 1);
        int k0 = ch * 32;
        #pragma unroll
        for (int k8 = 0; k8 < 4; k8++) {
            int kk = k8 * 8;
            float sv0 = 1.f, sv1 = 1.f;
            if (QKV_MODE) {
                sv0 = sS[k0 + kk + t];
                sv1 = sS[k0 + kk + t + 4];
            }
            uint32_t a[4][4];
            #pragma unroll
            for (int mt = 0; mt < 4; mt++) {
                const float* wr = ws + (wm + mt * 16) * G2_LDW + kk;
                float f0 = wr[g * G2_LDW + t];
                float f1 = wr[(g + 8) * G2_LDW + t];
                float f2 = wr[g * G2_LDW + t + 4];
                float f3 = wr[(g + 8) * G2_LDW + t + 4];
                if (QKV_MODE) { f0 *= sv0; f1 *= sv0; f2 *= sv1; f3 *= sv1; }
                a[mt][0] = __float_as_uint(f0);
                a[mt][1] = __float_as_uint(f1);
                a[mt][2] = __float_as_uint(f2);
                a[mt][3] = __float_as_uint(f3);
            }
            uint32_t bb[4][2];
            #pragma unroll
            for (int nt = 0; nt < 4; nt++) {
                const float* br = bs + kk * G2_LDB + wn + nt * 8 + g;
                bb[nt][0] = __float_as_uint(br[t * G2_LDB]);
                bb[nt][1] = __float_as_uint(br[(t + 4) * G2_LDB]);
            }
            #pragma unroll
            for (int mt = 0; mt < 4; mt++)
                #pragma unroll
                for (int nt = 0; nt < 4; nt++)
                    mma8(acc[mt][nt], a[mt][0], a[mt][1], a[mt][2], a[mt][3],
                         bb[nt][0], bb[nt][1]);
        }
        __syncthreads();
    }

    if (QKV_MODE && typ < 2) {
        // ---- transposed epilogue: Q/K -> g_qkT bf16 ----
        float* St = sm;   // [n 128][rloc 132]
        #pragma unroll
        for (int mt = 0; mt < 4; mt++) {
            int r0 = wm + mt * 16 + g;
            #pragma unroll
            for (int nt = 0; nt < 4; nt++) {
                int cc = wn + nt * 8 + 2 * t;
                St[cc * 132 + r0]           = acc[mt][nt][0];
                St[(cc + 1) * 132 + r0]     = acc[mt][nt][1];
                St[cc * 132 + r0 + 8]       = acc[mt][nt][2];
                St[(cc + 1) * 132 + r0 + 8] = acc[mt][nt][3];
            }
        }
        __syncthreads();
        float qs = (typ == 0) ? 0.125f : 1.f;
        int dl = (threadIdx.x & 15) * 4;
        int nb = threadIdx.x >> 4;
        #pragma unroll
        for (int h2 = 0; h2 < 2; h2++) {
            int chunk = typ + pair * 6 + h2 * 3;
            int head  = pair * 2 + h2;
            int slot  = head + (typ == 1 ? 4 : 0);
            int mloc  = h2 * 64 + dl;
            float4 bv = *(const float4*)&g_qb[b * 768 + chunk * 64 + dl];
            __nv_bfloat16* ob = g_qkT + ((size_t)b * 8 + slot) * NSP * HD;
            #pragma unroll
            for (int it = 0; it < 8; it++) {
                int n = nb + it * 16;
                float4 v = *(float4*)&St[n * 132 + mloc];
                v.x = (v.x + bv.x) * qs; v.y = (v.y + bv.y) * qs;
                v.z = (v.z + bv.z) * qs; v.w = (v.w + bv.w) * qs;
                __nv_bfloat162 lo = __floats2bfloat162_rn(v.x, v.y);
                __nv_bfloat162 hi = __floats2bfloat162_rn(v.z, v.w);
                uint2 pk = make_uint2(*(uint32_t*)&lo, *(uint32_t*)&hi);
                *(uint2*)(ob + (size_t)(n0 + n) * HD + dl) = pk;
            }
        }
    } else {
        // ---- normal epilogue: V (bf16 -> g_vT) or proj (fp32 + residual) ----
        float* Ss = sm;
        #pragma unroll
        for (int mt = 0; mt < 4; mt++) {
            int r0 = wm + mt * 16 + g;
            #pragma unroll
            for (int nt = 0; nt < 4; nt++) {
                int cc = wn + nt * 8 + 2 * t;
                *(float2*)(Ss + r0 * G2_LDE + cc)       = make_float2(acc[mt][nt][0], acc[mt][nt][1]);
                *(float2*)(Ss + (r0 + 8) * G2_LDE + cc) = make_float2(acc[mt][nt][2], acc[mt][nt][3]);
            }
        }
        __syncthreads();
        for (int idx = threadIdx.x; idx < 4096; idx += 256) {
            int row = idx >> 5, n4 = (idx & 31) * 4;
            int m = (row < 64) ? (mA + row) : (mB + row - 64);
            float4 v = *(float4*)(Ss + row * G2_LDE + n4);
            if (QKV_MODE) {
                float bv = g_qb[b * 768 + m];
                v.x += bv; v.y += bv; v.z += bv; v.w += bv;
                int head = m / 192;
                int dc = m - head * 192 - 128;
                __nv_bfloat16* ob = g_vT + ((size_t)(b * 4 + head) * HD + dc) * NSP;
                __nv_bfloat162 lo = __floats2bfloat162_rn(v.x, v.y);
                __nv_bfloat162 hi = __floats2bfloat162_rn(v.z, v.w);
                uint2 pk = make_uint2(*(uint32_t*)&lo, *(uint32_t*)&hi);
                *(uint2*)(ob + n0 + n4) = pk;
            } else {
                float bv = bias[m];
                float4 rr = *(const float4*)(resid + ((size_t)b * MOUT + m) * NSP + n0 + n4);
                v.x += bv + rr.x; v.y += bv + rr.y;
                v.z += bv + rr.z; v.w += bv + rr.w;
                *(float4*)(out + ((size_t)b * MOUT + m) * NSP + n0 + n4) = v;
            }
        }
    }
}

// ---------------------------------------------------------------------------
// Flash attention v6: bf16 operands, m16n8k16 mma, native b16 ldmatrix.
// Q frags register-resident; K/V cp.async double-buffered; P bf16 warp-private.
// Layout stride 72 bf16 (144B) -> conflict-free LDSM.
// ---------------------------------------------------------------------------
#define BLD 72
#define BKBUF (64 * BLD)                  // bf16 elems per K/V buf (9216 B)
#define BK_OFF 0                          // bytes
#define BV_OFF 18432
#define BP_OFF 36864
#define AT6_BYTES (BP_OFF + 128 * BLD * 2)   // 55296 B

__global__ void __launch_bounds__(256, 2)
attn_v6() {
    extern __shared__ char smc[];
    __nv_bfloat16* KB = (__nv_bfloat16*)(smc + BK_OFF);
    __nv_bfloat16* VB = (__nv_bfloat16*)(smc + BV_OFF);
    __nv_bfloat16* Ps = (__nv_bfloat16*)(smc + BP_OFF);

    int qt = blockIdx.x, hh = blockIdx.y, b = blockIdx.z;
    const __nv_bfloat16* qTb = g_qkT + ((size_t)b * 8 + hh) * NSP * HD;
    const __nv_bfloat16* kTb = g_qkT + ((size_t)b * 8 + 4 + hh) * NSP * HD;
    const __nv_bfloat16* vT  = g_vT  + ((size_t)b * 4 + hh) * HD * NSP;
    int n0 = qt * 128;

    int lane = threadIdx.x & 31, warp = threadIdx.x >> 5;
    int g = lane >> 2, t = lane & 3;
    int iw = warp * 16;
    int idx = threadIdx.x;

    // A-pattern (row-major [m][k]): rows lane&15, col-half lane>>4
    int a_row = lane & 15, a_c16 = lane >> 4;
    // B-pattern ([n][k] rows): rows (lane&7)+((lane>>4)<<3), k-half (lane>>3)&1
    int b_row = (lane & 7) + ((lane >> 4) << 3);
    int b_c16 = (lane >> 3) & 1;

    uint32_t sm_u = (uint32_t)__cvta_generic_to_shared(smc);
    uint32_t pA  = sm_u + BP_OFF + ((iw + a_row) * BLD + a_c16 * 8) * 2;
    uint32_t kB0 = sm_u + BK_OFF + (b_row * BLD + b_c16 * 8) * 2;
    uint32_t vB0 = sm_u + BV_OFF + (b_row * BLD + b_c16 * 8) * 2;

    auto issue = [&](int tile) {
        __nv_bfloat16* kd = KB + (tile & 1) * BKBUF;
        __nv_bfloat16* vd = VB + (tile & 1) * BKBUF;
        int j0 = tile * 64;
        #pragma unroll
        for (int i2 = idx; i2 < 512; i2 += 256) {
            int r = i2 >> 3, c = (i2 & 7) * 8;
            __pipeline_memcpy_async(kd + r * BLD + c, kTb + (size_t)(j0 + r) * HD + c, 16);
            __pipeline_memcpy_async(vd + r * BLD + c, vT + (size_t)r * NSP + j0 + c, 16);
        }
        __pipeline_commit();
    };

    // Prologue: Q (bf16, pre-scaled/transposed) into P region; K/V tiles 0,1
    #pragma unroll
    for (int i2 = idx; i2 < 1024; i2 += 256) {
        int r = i2 >> 3, c = (i2 & 7) * 8;
        __pipeline_memcpy_async(Ps + r * BLD + c, qTb + (size_t)(n0 + r) * HD + c, 16);
    }
    __pipeline_commit();
    issue(0);
    issue(1);
    __pipeline_wait_prior(0);
    __syncthreads();

    // Hoist Q fragments (4 chunks of k16) into 16 registers
    uint32_t qa[4][4];
    #pragma unroll
    for (int k16 = 0; k16 < 4; k16++)
        ldsm4(qa[k16][0], qa[k16][1], qa[k16][2], qa[k16][3], pA + k16 * 32);

    float o[8][4];
    #pragma unroll
    for (int n = 0; n < 8; n++)
        #pragma unroll
        for (int c = 0; c < 4; c++) o[n][c] = 0.f;
    float m0 = -INFINITY, m1 = -INFINITY, l0 = 0.f, l1 = 0.f;

    for (int tile = 0; tile < 16; tile++) {
        __pipeline_wait_prior(1);
        __syncthreads();
        uint32_t bufo = (tile & 1) * BKBUF * 2;
        uint32_t kB = kB0 + bufo;
        uint32_t vB = vB0 + bufo;

        // S = Q K^T (Q frags in regs; K via LDSM, [j][d] rows)
        float s[8][4];
        #pragma unroll
        for (int n = 0; n < 8; n++)
            #pragma unroll
            for (int c = 0; c < 4; c++) s[n][c] = 0.f;
        #pragma unroll
        for (int k16 = 0; k16 < 4; k16++) {
            #pragma unroll
            for (int np = 0; np < 4; np++) {
                uint32_t b0, b1, b2, b3;
                ldsm4(b0, b1, b2, b3, kB + (np * 16 * BLD + k16 * 16) * 2);
                mmabf(s[2 * np],     qa[k16][0], qa[k16][1], qa[k16][2], qa[k16][3], b0, b1);
                mmabf(s[2 * np + 1], qa[k16][0], qa[k16][1], qa[k16][2], qa[k16][3], b2, b3);
            }
        }

        // In-register online softmax (fp32)
        float mx0 = -INFINITY, mx1 = -INFINITY;
        #pragma unroll
        for (int n = 0; n < 8; n++) {
            mx0 = fmaxf(mx0, fmaxf(s[n][0], s[n][1]));
            mx1 = fmaxf(mx1, fmaxf(s[n][2], s[n][3]));
        }
        mx0 = fmaxf(mx0, __shfl_xor_sync(0xffffffffu, mx0, 1));
        mx0 = fmaxf(mx0, __shfl_xor_sync(0xffffffffu, mx0, 2));
        mx1 = fmaxf(mx1, __shfl_xor_sync(0xffffffffu, mx1, 1));
        mx1 = fmaxf(mx1, __shfl_xor_sync(0xffffffffu, mx1, 2));
        float mn0 = fmaxf(m0, mx0), mn1 = fmaxf(m1, mx1);
        float al0 = __expf(m0 - mn0), al1 = __expf(m1 - mn1);
        m0 = mn0; m1 = mn1;
        float r0 = 0.f, r1 = 0.f;
        #pragma unroll
        for (int n = 0; n < 8; n++) {
            s[n][0] = __expf(s[n][0] - mn0);
            s[n][1] = __expf(s[n][1] - mn0);
            s[n][2] = __expf(s[n][2] - mn1);
            s[n][3] = __expf(s[n][3] - mn1);
            r0 += s[n][0] + s[n][1];
            r1 += s[n][2] + s[n][3];
        }
        r0 += __shfl_xor_sync(0xffffffffu, r0, 1);
        r0 += __shfl_xor_sync(0xffffffffu, r0, 2);
        r1 += __shfl_xor_sync(0xffffffffu, r1, 1);
        r1 += __shfl_xor_sync(0xffffffffu, r1, 2);
        l0 = l0 * al0 + r0;
        l1 = l1 * al1 + r1;

        // Store P as bf16 (warp-private rows)
        #pragma unroll
        for (int n = 0; n < 8; n++) {
            __nv_bfloat162 lo = __floats2bfloat162_rn(s[n][0], s[n][1]);
            __nv_bfloat162 hi = __floats2bfloat162_rn(s[n][2], s[n][3]);
            *(__nv_bfloat162*)(Ps + (iw + g)     * BLD + n * 8 + 2 * t) = lo;
            *(__nv_bfloat162*)(Ps + (iw + g + 8) * BLD + n * 8 + 2 * t) = hi;
        }
        __syncwarp();

        // Rescale O
        #pragma unroll
        for (int n = 0; n < 8; n++) {
            o[n][0] *= al0; o[n][1] *= al0;
            o[n][2] *= al1; o[n][3] *= al1;
        }

        // O += P V^T (P A-frags via LDSM; V [dc][j] rows = B-pattern)
        #pragma unroll
        for (int j16 = 0; j16 < 4; j16++) {
            uint32_t a0, a1, a2, a3;
            ldsm4(a0, a1, a2, a3, pA + j16 * 32);
            #pragma unroll
            for (int np = 0; np < 4; np++) {
                uint32_t b0, b1, b2, b3;
                ldsm4(b0, b1, b2, b3, vB + (np * 16 * BLD + j16 * 16) * 2);
                mmabf(o[2 * np],     a0, a1, a2, a3, b0, b1);
                mmabf(o[2 * np + 1], a0, a1, a2, a3, b2, b3);
            }
        }
        __syncthreads();
        if (tile < 14) issue(tile + 2);
    }

    // Normalize; stage transposed [dc][i] fp32 in K/V region (now free)
    float inv0 = 1.f / l0, inv1 = 1.f / l1;
    #pragma unroll
    for (int n = 0; n < 8; n++) {
        o[n][0] *= inv0; o[n][1] *= inv0;
        o[n][2] *= inv1; o[n][3] *= inv1;
    }
    float* Os = (float*)smc;   // 64 x 132 fp32 = 33792 B <= 36864 B (K+V bufs)
    #pragma unroll
    for (int n = 0; n < 8; n++) {
        int dc = n * 8 + 2 * t;
        Os[dc * 132 + iw + g]           = o[n][0];
        Os[(dc + 1) * 132 + iw + g]     = o[n][1];
        Os[dc * 132 + iw + g + 8]       = o[n][2];
        Os[(dc + 1) * 132 + iw + g + 8] = o[n][3];
    }
    __syncthreads();
    float* ob = g_att + ((size_t)b * CH + hh * HD) * NSP + n0;
    for (int i2 = threadIdx.x; i2 < 2048; i2 += 256) {
        int dc = i2 >> 5, i4 = (i2 & 31) * 4;
        *(float4*)(ob + (size_t)dc * NSP + i4) = *(float4*)(Os + dc * 132 + i4);
    }
}

// ---------------------------------------------------------------------------

extern "C" void kernel_launch(void* const* d_in, const int* in_sizes, int n_in,
                              void* d_out, int out_size) {
    const float* x      = (const float*)d_in[0];
    const float* gamma  = (const float*)d_in[1];
    const float* beta   = (const float*)d_in[2];
    const float* qkv_w  = (const float*)d_in[3];
    const float* qkv_b  = (const float*)d_in[4];
    const float* proj_w = (const float*)d_in[5];
    const float* proj_b = (const float*)d_in[6];
    float* out = (float*)d_out;

    const int gm_smem  = G2_FLOATS * 4;
    const int att_smem = AT6_BYTES;

    cudaFuncSetAttribute(gemm_ptx<768, true>,
                         cudaFuncAttributeMaxDynamicSharedMemorySize, gm_smem);
    cudaFuncSetAttribute(gemm_ptx<256, false>,
                         cudaFuncAttributeMaxDynamicSharedMemorySize, gm_smem);
    cudaFuncSetAttribute(attn_v6,
                         cudaFuncAttributeMaxDynamicSharedMemorySize, att_smem);

    gn_stats<<<BATCH * NGRP, 256>>>(x, gamma, beta);
    qkv_bias_kernel<<<dim3(6, BATCH), 128>>>(qkv_w, qkv_b);
    gemm_ptx<768, true ><<<dim3(8, 6, BATCH), 256, gm_smem>>>(qkv_w, qkv_b /*unused*/, x, x /*unused*/, out /*unused*/);
    attn_v6<<<dim3(NSP / 128, NHEADS, BATCH), 256, att_smem>>>();
    gemm_ptx<256, false><<<dim3(8, 2, BATCH), 256, gm_smem>>>(proj_w, proj_b, x /*unused*/, x, out);
}